// round 1
// baseline (speedup 1.0000x reference)
#include <cuda_runtime.h>
#include <math.h>

// ---------------- problem constants ----------------
#define LNUM  6
#define D     1024
#define H     16
#define DKH   64
#define FFD   4096
#define TT    1024
#define BATCH 2
#define NTOK  (TT*BATCH)       // 2048 tokens
#define D3    (3*D)            // 3072
#define D2    (2*D)            // 2048
#define ATT_SCALE 0.125f       // 1/sqrt(64)

// ---------------- scratch (device globals; no allocs allowed) ----------------
__device__ float g_x   [NTOK*D];    // residual stream
__device__ float g_h   [NTOK*D];    // layernorm output
__device__ float g_qkv [NTOK*D3];
__device__ float g_a   [NTOK*D];    // attention output
__device__ float g_proj[NTOK*D];    // projection output (attn-out / ff2)
__device__ float g_cat [NTOK*D2];   // [x, y] concat for GRU gate
__device__ float g_gate[NTOK*D3];   // GRU gate pre-activation
__device__ float g_ff  [NTOK*FFD];  // FF hidden

// ---------------- generic GEMM: C[N,M] = A[N,K] @ W[M,K]^T (+ bias) ----------
// BM=BN=64, BK=16, 256 threads, 4x4 microtile per thread.
#define BM 64
#define BN 64
#define BK 16

__global__ __launch_bounds__(256)
void gemm_nt(const float* __restrict__ A, const float* __restrict__ W,
             const float* __restrict__ bias, float* __restrict__ C,
             int M, int K) {
    __shared__ float As[BK][BM + 4];
    __shared__ float Ws[BK][BN + 4];

    const int tid  = threadIdx.x;
    const int row0 = blockIdx.y * BM;
    const int col0 = blockIdx.x * BN;
    const int tx = tid & 15;         // 0..15
    const int ty = tid >> 4;         // 0..15
    const int lr = tid >> 2;         // 0..63 (tile row for loading)
    const int lk = (tid & 3) * 4;    // 0,4,8,12

    float acc[4][4];
#pragma unroll
    for (int i = 0; i < 4; i++)
#pragma unroll
        for (int j = 0; j < 4; j++) acc[i][j] = 0.f;

    const float* Ap = A + (size_t)(row0 + lr) * K + lk;
    const float* Wp = W + (size_t)(col0 + lr) * K + lk;

    for (int k0 = 0; k0 < K; k0 += BK) {
        float4 av = *(const float4*)(Ap + k0);
        float4 wv = *(const float4*)(Wp + k0);
        As[lk + 0][lr] = av.x; As[lk + 1][lr] = av.y;
        As[lk + 2][lr] = av.z; As[lk + 3][lr] = av.w;
        Ws[lk + 0][lr] = wv.x; Ws[lk + 1][lr] = wv.y;
        Ws[lk + 2][lr] = wv.z; Ws[lk + 3][lr] = wv.w;
        __syncthreads();

#pragma unroll
        for (int kk = 0; kk < BK; kk++) {
            float ar[4], br[4];
#pragma unroll
            for (int i = 0; i < 4; i++) ar[i] = As[kk][ty * 4 + i];
#pragma unroll
            for (int j = 0; j < 4; j++) br[j] = Ws[kk][tx * 4 + j];
#pragma unroll
            for (int i = 0; i < 4; i++)
#pragma unroll
                for (int j = 0; j < 4; j++) acc[i][j] += ar[i] * br[j];
        }
        __syncthreads();
    }

#pragma unroll
    for (int i = 0; i < 4; i++) {
        float* crow = C + (size_t)(row0 + ty * 4 + i) * M + col0 + tx * 4;
#pragma unroll
        for (int j = 0; j < 4; j++) {
            float v = acc[i][j];
            if (bias) v += bias[col0 + tx * 4 + j];
            crow[j] = v;
        }
    }
}

// ---------------- layernorm: one block per row ----------------
__global__ __launch_bounds__(256)
void ln_kernel(const float* __restrict__ x, const float* __restrict__ g,
               const float* __restrict__ b, float* __restrict__ out) {
    const int n = blockIdx.x;
    const float* xr = x + (size_t)n * D;
    const int tid = threadIdx.x;

    float s = 0.f, sq = 0.f;
    for (int j = tid; j < D; j += 256) { float v = xr[j]; s += v; sq += v * v; }

    __shared__ float rs[256], rq[256];
    rs[tid] = s; rq[tid] = sq; __syncthreads();
    for (int off = 128; off > 0; off >>= 1) {
        if (tid < off) { rs[tid] += rs[tid + off]; rq[tid] += rq[tid + off]; }
        __syncthreads();
    }
    const float mu  = rs[0] * (1.f / D);
    const float var = rq[0] * (1.f / D) - mu * mu;
    const float inv = rsqrtf(var + 1e-6f);

    float* orow = out + (size_t)n * D;
    for (int j = tid; j < D; j += 256)
        orow[j] = (xr[j] - mu) * inv * g[j] + b[j];
}

// ---------------- attention: one block per (t, b, h) ----------------
__global__ __launch_bounds__(256)
void attn_kernel(const float* __restrict__ qkv, float* __restrict__ a) {
    const int t  = blockIdx.x;
    const int bh = blockIdx.y;
    const int b  = bh / H;
    const int h  = bh % H;
    const int tid  = threadIdx.x;
    const int warp = tid >> 5;
    const int lane = tid & 31;

    __shared__ float q[DKH];
    __shared__ float sc[TT];
    __shared__ float red[256];
    __shared__ float accs[4][DKH];

    if (tid < DKH) q[tid] = qkv[((size_t)(t * BATCH + b)) * D3 + h * DKH + tid];
    __syncthreads();

    // scores (coalesced per warp over d)
    for (int s = warp; s <= t; s += 8) {
        const float* kp = qkv + ((size_t)(s * BATCH + b)) * D3 + D + h * DKH;
        float dot = q[lane] * kp[lane] + q[lane + 32] * kp[lane + 32];
#pragma unroll
        for (int off = 16; off > 0; off >>= 1)
            dot += __shfl_xor_sync(0xffffffffu, dot, off);
        if (lane == 0) sc[s] = dot * ATT_SCALE;
    }
    __syncthreads();

    // softmax over s <= t
    float m = -1e30f;
    for (int s = tid; s <= t; s += 256) m = fmaxf(m, sc[s]);
    red[tid] = m; __syncthreads();
    for (int off = 128; off > 0; off >>= 1) {
        if (tid < off) red[tid] = fmaxf(red[tid], red[tid + off]);
        __syncthreads();
    }
    const float mx = red[0];
    __syncthreads();

    float sum = 0.f;
    for (int s = tid; s <= t; s += 256) { float e = expf(sc[s] - mx); sc[s] = e; sum += e; }
    red[tid] = sum; __syncthreads();
    for (int off = 128; off > 0; off >>= 1) {
        if (tid < off) red[tid] += red[tid + off];
        __syncthreads();
    }
    const float invsum = 1.f / red[0];
    __syncthreads();

    // output accumulation, coalesced over d
    const int chunk = tid >> 6;   // 0..3
    const int d     = tid & 63;
    float acc = 0.f;
    for (int s = chunk; s <= t; s += 4)
        acc += sc[s] * qkv[((size_t)(s * BATCH + b)) * D3 + 2 * D + h * DKH + d];
    accs[chunk][d] = acc;
    __syncthreads();
    if (tid < DKH) {
        float r = (accs[0][tid] + accs[1][tid] + accs[2][tid] + accs[3][tid]) * invsum;
        a[((size_t)(t * BATCH + b)) * D + h * DKH + tid] = r;
    }
}

// ---------------- elementwise kernels ----------------
__device__ __forceinline__ float gelu_exact(float v) { return v * normcdff(v); }

__global__ void gelu_pe_kernel(float* __restrict__ x, const float* __restrict__ pe) {
    int idx = blockIdx.x * blockDim.x + threadIdx.x;
    if (idx >= NTOK * D) return;
    int t = idx / (BATCH * D);
    int d = idx % D;
    x[idx] = gelu_exact(x[idx]) + pe[t * D + d];
}

__global__ void gelu_kernel(float* __restrict__ x, int n) {
    int idx = blockIdx.x * blockDim.x + threadIdx.x;
    if (idx >= n) return;
    x[idx] = gelu_exact(x[idx]);
}

__global__ void concat_kernel(const float* __restrict__ x, const float* __restrict__ y,
                              float* __restrict__ cat) {
    int idx = blockIdx.x * blockDim.x + threadIdx.x;
    if (idx >= NTOK * D2) return;
    int n = idx / D2;
    int j = idx % D2;
    cat[idx] = (j < D) ? x[(size_t)n * D + j] : y[(size_t)n * D + (j - D)];
}

__global__ void gru_kernel(float* __restrict__ x, const float* __restrict__ gate,
                           const float* __restrict__ bg) {
    int idx = blockIdx.x * blockDim.x + threadIdx.x;
    if (idx >= NTOK * D) return;
    int n = idx / D;
    int j = idx % D;
    const float* grow = gate + (size_t)n * D3;
    float gr = grow[j];
    float gz = grow[D + j];
    float gh = grow[2 * D + j];
    float r = 1.f / (1.f + expf(-gr));
    float z = 1.f / (1.f + expf(-(gz - bg[j])));
    float hh = tanhf(gh * r);
    float xv = x[idx];
    x[idx] = (1.f - z) * xv + z * hh;
}

// ---------------- driver ----------------
extern "C" void kernel_launch(void* const* d_in, const int* in_sizes, int n_in,
                              void* d_out, int out_size) {
    const float* x_in  = (const float*)d_in[0];
    const float* pe    = (const float*)d_in[1];
    const float* in_w  = (const float*)d_in[2];
    const float* in_b  = (const float*)d_in[3];
    const float* qkv_w = (const float*)d_in[4];
    const float* out_w = (const float*)d_in[5];
    const float* out_b = (const float*)d_in[6];
    const float* ln1_g = (const float*)d_in[7];
    const float* ln1_b = (const float*)d_in[8];
    const float* ln2_g = (const float*)d_in[9];
    const float* ln2_b = (const float*)d_in[10];
    const float* ff_w1 = (const float*)d_in[11];
    const float* ff_b1 = (const float*)d_in[12];
    const float* ff_w2 = (const float*)d_in[13];
    const float* ff_b2 = (const float*)d_in[14];
    const float* g1_w  = (const float*)d_in[15];
    const float* g1_bg = (const float*)d_in[16];
    const float* g2_w  = (const float*)d_in[17];
    const float* g2_bg = (const float*)d_in[18];
    const float* on_g  = (const float*)d_in[19];
    const float* on_b  = (const float*)d_in[20];

    float *px, *ph, *pqkv, *pa, *pproj, *pcat, *pgate, *pff;
    cudaGetSymbolAddress((void**)&px,    g_x);
    cudaGetSymbolAddress((void**)&ph,    g_h);
    cudaGetSymbolAddress((void**)&pqkv,  g_qkv);
    cudaGetSymbolAddress((void**)&pa,    g_a);
    cudaGetSymbolAddress((void**)&pproj, g_proj);
    cudaGetSymbolAddress((void**)&pcat,  g_cat);
    cudaGetSymbolAddress((void**)&pgate, g_gate);
    cudaGetSymbolAddress((void**)&pff,   g_ff);

    const int EW = 256;
    dim3 gD   (D   / BN, NTOK / BM);
    dim3 gD3  (D3  / BN, NTOK / BM);
    dim3 gFF  (FFD / BN, NTOK / BM);

    // input projection + GELU + positional encoding
    gemm_nt<<<gD, 256>>>(x_in, in_w, in_b, px, D, D);
    gelu_pe_kernel<<<(NTOK * D + EW - 1) / EW, EW>>>(px, pe);

    for (int l = 0; l < LNUM; l++) {
        const float* qw  = qkv_w + (size_t)l * D3 * D;
        const float* ow  = out_w + (size_t)l * D * D;
        const float* ob  = out_b + (size_t)l * D;
        const float* l1g = ln1_g + (size_t)l * D;
        const float* l1b = ln1_b + (size_t)l * D;
        const float* l2g = ln2_g + (size_t)l * D;
        const float* l2b = ln2_b + (size_t)l * D;
        const float* f1  = ff_w1 + (size_t)l * FFD * D;
        const float* fb1 = ff_b1 + (size_t)l * FFD;
        const float* f2  = ff_w2 + (size_t)l * D * FFD;
        const float* fb2 = ff_b2 + (size_t)l * D;
        const float* gw1 = g1_w  + (size_t)l * D3 * D2;
        const float* gb1 = g1_bg + (size_t)l * D;
        const float* gw2 = g2_w  + (size_t)l * D3 * D2;
        const float* gb2 = g2_bg + (size_t)l * D;

        // attention block
        ln_kernel<<<NTOK, 256>>>(px, l1g, l1b, ph);
        gemm_nt<<<gD3, 256>>>(ph, qw, nullptr, pqkv, D3, D);
        attn_kernel<<<dim3(TT, BATCH * H), 256>>>(pqkv, pa);
        gemm_nt<<<gD, 256>>>(pa, ow, ob, pproj, D, D);
        concat_kernel<<<(NTOK * D2 + EW - 1) / EW, EW>>>(px, pproj, pcat);
        gemm_nt<<<gD3, 256>>>(pcat, gw1, nullptr, pgate, D3, D2);
        gru_kernel<<<(NTOK * D + EW - 1) / EW, EW>>>(px, pgate, gb1);

        // feed-forward block
        ln_kernel<<<NTOK, 256>>>(px, l2g, l2b, ph);
        gemm_nt<<<gFF, 256>>>(ph, f1, fb1, pff, FFD, D);
        gelu_kernel<<<(NTOK * FFD + EW - 1) / EW, EW>>>(pff, NTOK * FFD);
        gemm_nt<<<gD, 256>>>(pff, f2, fb2, pproj, D, FFD);
        concat_kernel<<<(NTOK * D2 + EW - 1) / EW, EW>>>(px, pproj, pcat);
        gemm_nt<<<gD3, 256>>>(pcat, gw2, nullptr, pgate, D3, D2);
        gru_kernel<<<(NTOK * D + EW - 1) / EW, EW>>>(px, pgate, gb2);
    }

    // final layernorm straight into d_out
    ln_kernel<<<NTOK, 256>>>(px, on_g, on_b, (float*)d_out);
}

// round 3
// speedup vs baseline: 2.0893x; 2.0893x over previous
#include <cuda_runtime.h>
#include <cuda_bf16.h>
#include <math.h>
#include <stdint.h>

// ---------------- problem constants ----------------
#define LNUM  6
#define D     1024
#define H     16
#define DKH   64
#define FFD   4096
#define TT    1024
#define BATCH 2
#define NTOK  2048
#define D3    3072
#define D2    2048
#define ATT_SCALE 0.125f

#define SWZ(o) ((o) ^ (((o) >> 3) & 0x70))

// ---------------- scratch (device globals; no allocs allowed) ----------------
__device__ float g_x   [NTOK*D];
__device__ float g_qkv [NTOK*D3];
__device__ float g_a   [NTOK*D];
__device__ float g_proj[NTOK*D];
__device__ float g_gate[NTOK*D3];
__device__ __nv_bfloat16 g_ahi[NTOK*D2], g_alo[NTOK*D2];
__device__ __nv_bfloat16 g_fhi[NTOK*FFD], g_flo[NTOK*FFD];
__device__ __nv_bfloat16 wb_in_hi [D*D],        wb_in_lo [D*D];
__device__ __nv_bfloat16 wb_qkv_hi[LNUM*D3*D],  wb_qkv_lo[LNUM*D3*D];
__device__ __nv_bfloat16 wb_out_hi[LNUM*D*D],   wb_out_lo[LNUM*D*D];
__device__ __nv_bfloat16 wb_f1_hi [LNUM*FFD*D], wb_f1_lo [LNUM*FFD*D];
__device__ __nv_bfloat16 wb_f2_hi [LNUM*D*FFD], wb_f2_lo [LNUM*D*FFD];
__device__ __nv_bfloat16 wb_g1_hi [LNUM*D3*D2], wb_g1_lo [LNUM*D3*D2];
__device__ __nv_bfloat16 wb_g2_hi [LNUM*D3*D2], wb_g2_lo [LNUM*D3*D2];

// ---------------- PTX helpers (portable: sm_80-level, no 'a' features) -------
__device__ __forceinline__ uint32_t smem_u32(const void* p) {
    uint32_t a;
    asm("{ .reg .u64 t; cvta.to.shared.u64 t, %1; cvt.u32.u64 %0, t; }" : "=r"(a) : "l"(p));
    return a;
}
__device__ __forceinline__ void cp16(uint32_t d, const void* g) {
    asm volatile("cp.async.cg.shared.global [%0], [%1], 16;" :: "r"(d), "l"(g));
}
__device__ __forceinline__ void ldm_x4(uint32_t* f, uint32_t addr) {
    asm volatile("ldmatrix.sync.aligned.m8n8.x4.shared.b16 {%0,%1,%2,%3}, [%4];"
                 : "=r"(f[0]), "=r"(f[1]), "=r"(f[2]), "=r"(f[3]) : "r"(addr));
}
__device__ __forceinline__ void mma16816(float* c, const uint32_t* a, uint32_t b0, uint32_t b1) {
    asm volatile(
        "mma.sync.aligned.m16n8k16.row.col.f32.bf16.bf16.f32 "
        "{%0,%1,%2,%3}, {%4,%5,%6,%7}, {%8,%9}, {%0,%1,%2,%3};"
        : "+f"(c[0]), "+f"(c[1]), "+f"(c[2]), "+f"(c[3])
        : "r"(a[0]), "r"(a[1]), "r"(a[2]), "r"(a[3]), "r"(b0), "r"(b1));
}

__device__ __forceinline__ float gelu_exact(float v) { return v * normcdff(v); }

// ---------------- bf16 hi/lo split GEMM via mma.sync ------------------------
// C[NTOK,ncols] = A[NTOK,K] @ W[ncols,K]^T, with A,W as hi/lo bf16 pairs.
// Computed as one GEMM over K' = 3K: segments (Ahi,Whi), (Ahi,Wlo), (Alo,Whi).
// mode 0: Cf = result (+bias). mode 1: gelu(result+bias) split into Chi/Clo.
// CTA tile 128x128, BK=64, 8 warps (each 32x64), double-buffered cp.async.
#define SMEM_STAGE 32768      // 16KB A + 16KB B
#define SMEM_BYTES (2*SMEM_STAGE)

__global__ __launch_bounds__(256)
void gemm_mma(const __nv_bfloat16* __restrict__ Ahi, const __nv_bfloat16* __restrict__ Alo,
              const __nv_bfloat16* __restrict__ Whi, const __nv_bfloat16* __restrict__ Wlo,
              const float* __restrict__ bias,
              float* __restrict__ Cf,
              __nv_bfloat16* __restrict__ Chi, __nv_bfloat16* __restrict__ Clo,
              int ncols, int K, int mode)
{
    extern __shared__ char smem[];
    const uint32_t sb = smem_u32(smem);
    const int tid  = threadIdx.x;
    const int wid  = tid >> 5;
    const int lane = tid & 31;
    const int wm   = wid >> 1;        // 0..3 -> 32-row slab
    const int wn   = wid & 1;         // 0..1 -> 64-col slab
    const int row0 = blockIdx.y * 128;
    const int col0 = blockIdx.x * 128;

    float acc[2][8][4];
#pragma unroll
    for (int i = 0; i < 2; i++)
#pragma unroll
        for (int g = 0; g < 8; g++)
#pragma unroll
            for (int q = 0; q < 4; q++) acc[i][g][q] = 0.f;

    // ldmatrix lane addressing (row-major tiles, SW128 swizzle)
    const int lr   = lane & 15;
    const int koff = (lane >> 4) << 4;     // +16B for upper half-warp
    uint32_t roffA[2], rxA[2], roffB[4], rxB[4];
#pragma unroll
    for (int i = 0; i < 2; i++) {
        int r = wm * 32 + i * 16 + lr;
        roffA[i] = r * 128; rxA[i] = (r & 7) << 4;
    }
#pragma unroll
    for (int j = 0; j < 4; j++) {
        int r = wn * 64 + j * 16 + lr;
        roffB[j] = r * 128; rxB[j] = (r & 7) << 4;
    }

    const int cpk = K / 64;         // chunks per segment
    const int nch = 3 * cpk;

    // tile loader: chunk cc -> stage
    auto issue = [&](int cc, int stage) {
        const int seg = cc / cpk;
        const int kbase = (cc % cpk) * 64;
        const __nv_bfloat16* A = (seg == 2) ? Alo : Ahi;
        const __nv_bfloat16* W = (seg == 1) ? Wlo : Whi;
        const uint32_t sA = sb + stage * SMEM_STAGE;
        const uint32_t sB = sA + 16384;
#pragma unroll
        for (int i = 0; i < 4; i++) {
            int idx = tid + i * 256;       // 0..1023
            int r = idx >> 3, c = idx & 7;
            uint32_t off = SWZ((uint32_t)(r * 128 + c * 16));
            cp16(sA + off, A + (size_t)(row0 + r) * K + kbase + c * 8);
            cp16(sB + off, W + (size_t)(col0 + r) * K + kbase + c * 8);
        }
        asm volatile("cp.async.commit_group;");
    };

    issue(0, 0);
    for (int cc = 0; cc < nch; cc++) {
        const int stage = cc & 1;
        asm volatile("cp.async.wait_group 0;");
        __syncthreads();
        if (cc + 1 < nch) issue(cc + 1, stage ^ 1);

        const uint32_t sA = sb + stage * SMEM_STAGE;
        const uint32_t sB = sA + 16384;
#pragma unroll
        for (int ks = 0; ks < 4; ks++) {
            const uint32_t kb = ks * 32 + koff;
            uint32_t a[2][4];
#pragma unroll
            for (int i = 0; i < 2; i++)
                ldm_x4(a[i], sA + roffA[i] + (kb ^ rxA[i]));
#pragma unroll
            for (int j = 0; j < 4; j++) {
                uint32_t b[4];
                ldm_x4(b, sB + roffB[j] + (kb ^ rxB[j]));
#pragma unroll
                for (int i = 0; i < 2; i++) {
                    mma16816(acc[i][j*2+0], a[i], b[0], b[2]);
                    mma16816(acc[i][j*2+1], a[i], b[1], b[3]);
                }
            }
        }
        __syncthreads();
    }

    // ---- epilogue ----
    const int rbase = row0 + wm * 32 + (lane >> 2);
    const int cbase = col0 + wn * 64 + (lane & 3) * 2;
#pragma unroll
    for (int i = 0; i < 2; i++) {
#pragma unroll
        for (int g = 0; g < 8; g++) {
            const int c = cbase + g * 8;
            const int r0 = rbase + i * 16;
            float b0 = bias ? bias[c]     : 0.f;
            float b1 = bias ? bias[c + 1] : 0.f;
            float v00 = acc[i][g][0] + b0, v01 = acc[i][g][1] + b1;
            float v10 = acc[i][g][2] + b0, v11 = acc[i][g][3] + b1;
            if (mode == 0) {
                *(float2*)(Cf + (size_t)r0 * ncols + c)       = make_float2(v00, v01);
                *(float2*)(Cf + (size_t)(r0+8) * ncols + c)   = make_float2(v10, v11);
            } else {
                v00 = gelu_exact(v00); v01 = gelu_exact(v01);
                v10 = gelu_exact(v10); v11 = gelu_exact(v11);
                __nv_bfloat16 h00 = __float2bfloat16(v00), h01 = __float2bfloat16(v01);
                __nv_bfloat16 h10 = __float2bfloat16(v10), h11 = __float2bfloat16(v11);
                __nv_bfloat16 l00 = __float2bfloat16(v00 - __bfloat162float(h00));
                __nv_bfloat16 l01 = __float2bfloat16(v01 - __bfloat162float(h01));
                __nv_bfloat16 l10 = __float2bfloat16(v10 - __bfloat162float(h10));
                __nv_bfloat16 l11 = __float2bfloat16(v11 - __bfloat162float(h11));
                *(__nv_bfloat162*)(Chi + (size_t)r0 * ncols + c)     = __halves2bfloat162(h00, h01);
                *(__nv_bfloat162*)(Chi + (size_t)(r0+8) * ncols + c) = __halves2bfloat162(h10, h11);
                *(__nv_bfloat162*)(Clo + (size_t)r0 * ncols + c)     = __halves2bfloat162(l00, l01);
                *(__nv_bfloat162*)(Clo + (size_t)(r0+8) * ncols + c) = __halves2bfloat162(l10, l11);
            }
        }
    }
}

// ---------------- layernorm -> hi/lo bf16 split ----------------
__global__ __launch_bounds__(256)
void ln_split(const float* __restrict__ x, const float* __restrict__ g,
              const float* __restrict__ b,
              __nv_bfloat16* __restrict__ hi, __nv_bfloat16* __restrict__ lo) {
    const int n = blockIdx.x;
    const float* xr = x + (size_t)n * D;
    const int tid = threadIdx.x;

    float s = 0.f, sq = 0.f;
    for (int j = tid; j < D; j += 256) { float v = xr[j]; s += v; sq += v * v; }
    __shared__ float rs[256], rq[256];
    rs[tid] = s; rq[tid] = sq; __syncthreads();
    for (int off = 128; off > 0; off >>= 1) {
        if (tid < off) { rs[tid] += rs[tid + off]; rq[tid] += rq[tid + off]; }
        __syncthreads();
    }
    const float mu  = rs[0] * (1.f / D);
    const float var = rq[0] * (1.f / D) - mu * mu;
    const float inv = rsqrtf(var + 1e-6f);

    for (int j = tid; j < D; j += 256) {
        float v = (xr[j] - mu) * inv * g[j] + b[j];
        __nv_bfloat16 h = __float2bfloat16(v);
        hi[(size_t)n * D + j] = h;
        lo[(size_t)n * D + j] = __float2bfloat16(v - __bfloat162float(h));
    }
}

// ---------------- plain f32 layernorm (final output) ----------------
__global__ __launch_bounds__(256)
void ln_kernel(const float* __restrict__ x, const float* __restrict__ g,
               const float* __restrict__ b, float* __restrict__ out) {
    const int n = blockIdx.x;
    const float* xr = x + (size_t)n * D;
    const int tid = threadIdx.x;

    float s = 0.f, sq = 0.f;
    for (int j = tid; j < D; j += 256) { float v = xr[j]; s += v; sq += v * v; }
    __shared__ float rs[256], rq[256];
    rs[tid] = s; rq[tid] = sq; __syncthreads();
    for (int off = 128; off > 0; off >>= 1) {
        if (tid < off) { rs[tid] += rs[tid + off]; rq[tid] += rq[tid + off]; }
        __syncthreads();
    }
    const float mu  = rs[0] * (1.f / D);
    const float var = rq[0] * (1.f / D) - mu * mu;
    const float inv = rsqrtf(var + 1e-6f);

    float* orow = out + (size_t)n * D;
    for (int j = tid; j < D; j += 256)
        orow[j] = (xr[j] - mu) * inv * g[j] + b[j];
}

// ---------------- attention: one block per (t, b, h) ----------------
__global__ __launch_bounds__(256)
void attn_kernel(const float* __restrict__ qkv, float* __restrict__ a) {
    const int t  = blockIdx.x;
    const int bh = blockIdx.y;
    const int b  = bh / H;
    const int h  = bh % H;
    const int tid  = threadIdx.x;
    const int warp = tid >> 5;
    const int lane = tid & 31;

    __shared__ float q[DKH];
    __shared__ float sc[TT];
    __shared__ float red[256];
    __shared__ float accs[4][DKH];

    if (tid < DKH) q[tid] = qkv[((size_t)(t * BATCH + b)) * D3 + h * DKH + tid];
    __syncthreads();

    for (int s = warp; s <= t; s += 8) {
        const float* kp = qkv + ((size_t)(s * BATCH + b)) * D3 + D + h * DKH;
        float dot = q[lane] * kp[lane] + q[lane + 32] * kp[lane + 32];
#pragma unroll
        for (int off = 16; off > 0; off >>= 1)
            dot += __shfl_xor_sync(0xffffffffu, dot, off);
        if (lane == 0) sc[s] = dot * ATT_SCALE;
    }
    __syncthreads();

    float m = -1e30f;
    for (int s = tid; s <= t; s += 256) m = fmaxf(m, sc[s]);
    red[tid] = m; __syncthreads();
    for (int off = 128; off > 0; off >>= 1) {
        if (tid < off) red[tid] = fmaxf(red[tid], red[tid + off]);
        __syncthreads();
    }
    const float mx = red[0];
    __syncthreads();

    float sum = 0.f;
    for (int s = tid; s <= t; s += 256) { float e = expf(sc[s] - mx); sc[s] = e; sum += e; }
    red[tid] = sum; __syncthreads();
    for (int off = 128; off > 0; off >>= 1) {
        if (tid < off) red[tid] += red[tid + off];
        __syncthreads();
    }
    const float invsum = 1.f / red[0];
    __syncthreads();

    const int chunk = tid >> 6;
    const int d     = tid & 63;
    float acc = 0.f;
    for (int s = chunk; s <= t; s += 4)
        acc += sc[s] * qkv[((size_t)(s * BATCH + b)) * D3 + 2 * D + h * DKH + d];
    accs[chunk][d] = acc;
    __syncthreads();
    if (tid < DKH) {
        float r = (accs[0][tid] + accs[1][tid] + accs[2][tid] + accs[3][tid]) * invsum;
        a[((size_t)(t * BATCH + b)) * D + h * DKH + tid] = r;
    }
}

// ---------------- elementwise kernels ----------------
__global__ void gelu_pe_kernel(float* __restrict__ x, const float* __restrict__ pe) {
    int idx = blockIdx.x * blockDim.x + threadIdx.x;
    if (idx >= NTOK * D) return;
    int t = idx / (BATCH * D);
    int d = idx % D;
    x[idx] = gelu_exact(x[idx]) + pe[t * D + d];
}

__global__ void gru_kernel(float* __restrict__ x, const float* __restrict__ gate,
                           const float* __restrict__ bg) {
    int idx = blockIdx.x * blockDim.x + threadIdx.x;
    if (idx >= NTOK * D) return;
    int n = idx / D;
    int j = idx % D;
    const float* grow = gate + (size_t)n * D3;
    float gr = grow[j];
    float gz = grow[D + j];
    float gh = grow[2 * D + j];
    float r = 1.f / (1.f + expf(-gr));
    float z = 1.f / (1.f + expf(-(gz - bg[j])));
    float hh = tanhf(gh * r);
    float xv = x[idx];
    x[idx] = (1.f - z) * xv + z * hh;
}

// f32 array -> hi/lo bf16 split, 4 elems/thread
__global__ void cvt_split4(const float4* __restrict__ x,
                           __nv_bfloat162* __restrict__ hi, __nv_bfloat162* __restrict__ lo,
                           int n4) {
    int i = blockIdx.x * blockDim.x + threadIdx.x;
    if (i >= n4) return;
    float4 v = x[i];
    __nv_bfloat16 h0 = __float2bfloat16(v.x), h1 = __float2bfloat16(v.y);
    __nv_bfloat16 h2 = __float2bfloat16(v.z), h3 = __float2bfloat16(v.w);
    __nv_bfloat16 l0 = __float2bfloat16(v.x - __bfloat162float(h0));
    __nv_bfloat16 l1 = __float2bfloat16(v.y - __bfloat162float(h1));
    __nv_bfloat16 l2 = __float2bfloat16(v.z - __bfloat162float(h2));
    __nv_bfloat16 l3 = __float2bfloat16(v.w - __bfloat162float(h3));
    hi[2*i]   = __halves2bfloat162(h0, h1);
    hi[2*i+1] = __halves2bfloat162(h2, h3);
    lo[2*i]   = __halves2bfloat162(l0, l1);
    lo[2*i+1] = __halves2bfloat162(l2, l3);
}

// concat [x, y] rows (each D) -> hi/lo bf16 [NTOK][2D]
__global__ void cvt_concat4(const float* __restrict__ x, const float* __restrict__ y,
                            __nv_bfloat162* __restrict__ hi, __nv_bfloat162* __restrict__ lo) {
    int i = blockIdx.x * blockDim.x + threadIdx.x;
    if (i >= NTOK * D2 / 4) return;
    int e = i * 4;
    int n = e / D2;
    int j = e % D2;
    const float* src = (j < D) ? (x + (size_t)n * D + j) : (y + (size_t)n * D + (j - D));
    float4 v = *(const float4*)src;
    __nv_bfloat16 h0 = __float2bfloat16(v.x), h1 = __float2bfloat16(v.y);
    __nv_bfloat16 h2 = __float2bfloat16(v.z), h3 = __float2bfloat16(v.w);
    __nv_bfloat16 l0 = __float2bfloat16(v.x - __bfloat162float(h0));
    __nv_bfloat16 l1 = __float2bfloat16(v.y - __bfloat162float(h1));
    __nv_bfloat16 l2 = __float2bfloat16(v.z - __bfloat162float(h2));
    __nv_bfloat16 l3 = __float2bfloat16(v.w - __bfloat162float(h3));
    hi[2*i]   = __halves2bfloat162(h0, h1);
    hi[2*i+1] = __halves2bfloat162(h2, h3);
    lo[2*i]   = __halves2bfloat162(l0, l1);
    lo[2*i+1] = __halves2bfloat162(l2, l3);
}

// ---------------- driver ----------------
extern "C" void kernel_launch(void* const* d_in, const int* in_sizes, int n_in,
                              void* d_out, int out_size) {
    const float* x_in  = (const float*)d_in[0];
    const float* pe    = (const float*)d_in[1];
    const float* in_w  = (const float*)d_in[2];
    const float* in_b  = (const float*)d_in[3];
    const float* qkv_w = (const float*)d_in[4];
    const float* out_w = (const float*)d_in[5];
    const float* out_b = (const float*)d_in[6];
    const float* ln1_g = (const float*)d_in[7];
    const float* ln1_b = (const float*)d_in[8];
    const float* ln2_g = (const float*)d_in[9];
    const float* ln2_b = (const float*)d_in[10];
    const float* ff_w1 = (const float*)d_in[11];
    const float* ff_b1 = (const float*)d_in[12];
    const float* ff_w2 = (const float*)d_in[13];
    const float* ff_b2 = (const float*)d_in[14];
    const float* g1_w  = (const float*)d_in[15];
    const float* g1_bg = (const float*)d_in[16];
    const float* g2_w  = (const float*)d_in[17];
    const float* g2_bg = (const float*)d_in[18];
    const float* on_g  = (const float*)d_in[19];
    const float* on_b  = (const float*)d_in[20];

    float *px, *pqkv, *pa, *pproj, *pgate;
    __nv_bfloat16 *ahi, *alo, *fhi, *flo;
    __nv_bfloat16 *w_in_h, *w_in_l, *w_qkv_h, *w_qkv_l, *w_out_h, *w_out_l;
    __nv_bfloat16 *w_f1_h, *w_f1_l, *w_f2_h, *w_f2_l, *w_g1_h, *w_g1_l, *w_g2_h, *w_g2_l;
    cudaGetSymbolAddress((void**)&px,    g_x);
    cudaGetSymbolAddress((void**)&pqkv,  g_qkv);
    cudaGetSymbolAddress((void**)&pa,    g_a);
    cudaGetSymbolAddress((void**)&pproj, g_proj);
    cudaGetSymbolAddress((void**)&pgate, g_gate);
    cudaGetSymbolAddress((void**)&ahi,   g_ahi);
    cudaGetSymbolAddress((void**)&alo,   g_alo);
    cudaGetSymbolAddress((void**)&fhi,   g_fhi);
    cudaGetSymbolAddress((void**)&flo,   g_flo);
    cudaGetSymbolAddress((void**)&w_in_h,  wb_in_hi);  cudaGetSymbolAddress((void**)&w_in_l,  wb_in_lo);
    cudaGetSymbolAddress((void**)&w_qkv_h, wb_qkv_hi); cudaGetSymbolAddress((void**)&w_qkv_l, wb_qkv_lo);
    cudaGetSymbolAddress((void**)&w_out_h, wb_out_hi); cudaGetSymbolAddress((void**)&w_out_l, wb_out_lo);
    cudaGetSymbolAddress((void**)&w_f1_h,  wb_f1_hi);  cudaGetSymbolAddress((void**)&w_f1_l,  wb_f1_lo);
    cudaGetSymbolAddress((void**)&w_f2_h,  wb_f2_hi);  cudaGetSymbolAddress((void**)&w_f2_l,  wb_f2_lo);
    cudaGetSymbolAddress((void**)&w_g1_h,  wb_g1_hi);  cudaGetSymbolAddress((void**)&w_g1_l,  wb_g1_lo);
    cudaGetSymbolAddress((void**)&w_g2_h,  wb_g2_hi);  cudaGetSymbolAddress((void**)&w_g2_l,  wb_g2_lo);

    cudaFuncSetAttribute(gemm_mma, cudaFuncAttributeMaxDynamicSharedMemorySize, SMEM_BYTES);

    const int EW = 256;
    auto cvtgrid = [](int n) { return (n / 4 + 255) / 256; };

    // ---- weight hi/lo splits ----
    cvt_split4<<<cvtgrid(D*D),        EW>>>((const float4*)in_w,  (__nv_bfloat162*)w_in_h,  (__nv_bfloat162*)w_in_l,  D*D/4);
    cvt_split4<<<cvtgrid(LNUM*D3*D),  EW>>>((const float4*)qkv_w, (__nv_bfloat162*)w_qkv_h, (__nv_bfloat162*)w_qkv_l, LNUM*D3*D/4);
    cvt_split4<<<cvtgrid(LNUM*D*D),   EW>>>((const float4*)out_w, (__nv_bfloat162*)w_out_h, (__nv_bfloat162*)w_out_l, LNUM*D*D/4);
    cvt_split4<<<cvtgrid(LNUM*FFD*D), EW>>>((const float4*)ff_w1, (__nv_bfloat162*)w_f1_h,  (__nv_bfloat162*)w_f1_l,  LNUM*FFD*D/4);
    cvt_split4<<<cvtgrid(LNUM*D*FFD), EW>>>((const float4*)ff_w2, (__nv_bfloat162*)w_f2_h,  (__nv_bfloat162*)w_f2_l,  LNUM*D*FFD/4);
    cvt_split4<<<cvtgrid(LNUM*D3*D2), EW>>>((const float4*)g1_w,  (__nv_bfloat162*)w_g1_h,  (__nv_bfloat162*)w_g1_l,  LNUM*D3*D2/4);
    cvt_split4<<<cvtgrid(LNUM*D3*D2), EW>>>((const float4*)g2_w,  (__nv_bfloat162*)w_g2_h,  (__nv_bfloat162*)w_g2_l,  LNUM*D3*D2/4);

    dim3 gD  (D/128,   NTOK/128);
    dim3 gD3 (D3/128,  NTOK/128);
    dim3 gFF (FFD/128, NTOK/128);

    // ---- input projection + GELU + positional encoding ----
    cvt_split4<<<cvtgrid(NTOK*D), EW>>>((const float4*)x_in, (__nv_bfloat162*)ahi, (__nv_bfloat162*)alo, NTOK*D/4);
    gemm_mma<<<gD, 256, SMEM_BYTES>>>(ahi, alo, w_in_h, w_in_l, in_b, px, 0, 0, D, D, 0);
    gelu_pe_kernel<<<(NTOK*D + EW - 1)/EW, EW>>>(px, pe);

    for (int l = 0; l < LNUM; l++) {
        const __nv_bfloat16* qwh = w_qkv_h + (size_t)l*D3*D;  const __nv_bfloat16* qwl = w_qkv_l + (size_t)l*D3*D;
        const __nv_bfloat16* owh = w_out_h + (size_t)l*D*D;   const __nv_bfloat16* owl = w_out_l + (size_t)l*D*D;
        const __nv_bfloat16* f1h = w_f1_h  + (size_t)l*FFD*D; const __nv_bfloat16* f1l = w_f1_l  + (size_t)l*FFD*D;
        const __nv_bfloat16* f2h = w_f2_h  + (size_t)l*D*FFD; const __nv_bfloat16* f2l = w_f2_l  + (size_t)l*D*FFD;
        const __nv_bfloat16* g1h = w_g1_h  + (size_t)l*D3*D2; const __nv_bfloat16* g1l = w_g1_l  + (size_t)l*D3*D2;
        const __nv_bfloat16* g2h = w_g2_h  + (size_t)l*D3*D2; const __nv_bfloat16* g2l = w_g2_l  + (size_t)l*D3*D2;
        const float* ob  = out_b + (size_t)l*D;
        const float* l1g = ln1_g + (size_t)l*D;  const float* l1b = ln1_b + (size_t)l*D;
        const float* l2g = ln2_g + (size_t)l*D;  const float* l2b = ln2_b + (size_t)l*D;
        const float* fb1 = ff_b1 + (size_t)l*FFD;
        const float* fb2 = ff_b2 + (size_t)l*D;
        const float* gb1 = g1_bg + (size_t)l*D;
        const float* gb2 = g2_bg + (size_t)l*D;

        // attention block
        ln_split<<<NTOK, 256>>>(px, l1g, l1b, ahi, alo);
        gemm_mma<<<gD3, 256, SMEM_BYTES>>>(ahi, alo, qwh, qwl, nullptr, pqkv, 0, 0, D3, D, 0);
        attn_kernel<<<dim3(TT, BATCH*H), 256>>>(pqkv, pa);
        cvt_split4<<<cvtgrid(NTOK*D), EW>>>((const float4*)pa, (__nv_bfloat162*)ahi, (__nv_bfloat162*)alo, NTOK*D/4);
        gemm_mma<<<gD, 256, SMEM_BYTES>>>(ahi, alo, owh, owl, ob, pproj, 0, 0, D, D, 0);
        cvt_concat4<<<(NTOK*D2/4 + EW - 1)/EW, EW>>>(px, pproj, (__nv_bfloat162*)ahi, (__nv_bfloat162*)alo);
        gemm_mma<<<gD3, 256, SMEM_BYTES>>>(ahi, alo, g1h, g1l, nullptr, pgate, 0, 0, D3, D2, 0);
        gru_kernel<<<(NTOK*D + EW - 1)/EW, EW>>>(px, pgate, gb1);

        // feed-forward block
        ln_split<<<NTOK, 256>>>(px, l2g, l2b, ahi, alo);
        gemm_mma<<<gFF, 256, SMEM_BYTES>>>(ahi, alo, f1h, f1l, fb1, nullptr, fhi, flo, FFD, D, 1);
        gemm_mma<<<gD, 256, SMEM_BYTES>>>(fhi, flo, f2h, f2l, fb2, pproj, 0, 0, D, FFD, 0);
        cvt_concat4<<<(NTOK*D2/4 + EW - 1)/EW, EW>>>(px, pproj, (__nv_bfloat162*)ahi, (__nv_bfloat162*)alo);
        gemm_mma<<<gD3, 256, SMEM_BYTES>>>(ahi, alo, g2h, g2l, nullptr, pgate, 0, 0, D3, D2, 0);
        gru_kernel<<<(NTOK*D + EW - 1)/EW, EW>>>(px, pgate, gb2);
    }

    ln_kernel<<<NTOK, 256>>>(px, on_g, on_b, (float*)d_out);
}

// round 4
// speedup vs baseline: 3.0310x; 1.4507x over previous
#include <cuda_runtime.h>
#include <cuda_bf16.h>
#include <math.h>
#include <stdint.h>

// ---------------- problem constants ----------------
#define LNUM  6
#define D     1024
#define H     16
#define DKH   64
#define FFD   4096
#define TT    1024
#define BATCH 2
#define NTOK  2048
#define D3    3072
#define D2    2048
#define ATT_SCALE 0.125f

#define SWZ(o) ((o) ^ (((o) >> 3) & 0x70))

// ---------------- scratch (device globals; no allocs allowed) ----------------
__device__ float g_x   [NTOK*D];
__device__ float g_qkv [NTOK*D3];
__device__ float g_a   [NTOK*D];
__device__ float g_proj[NTOK*D];
__device__ float g_gate[NTOK*D3];
__device__ __nv_bfloat16 g_ahi[NTOK*D2], g_alo[NTOK*D2];
__device__ __nv_bfloat16 g_fhi[NTOK*FFD], g_flo[NTOK*FFD];
__device__ __nv_bfloat16 wb_in_hi [D*D],        wb_in_lo [D*D];
__device__ __nv_bfloat16 wb_qkv_hi[LNUM*D3*D],  wb_qkv_lo[LNUM*D3*D];
__device__ __nv_bfloat16 wb_out_hi[LNUM*D*D],   wb_out_lo[LNUM*D*D];
__device__ __nv_bfloat16 wb_f1_hi [LNUM*FFD*D], wb_f1_lo [LNUM*FFD*D];
__device__ __nv_bfloat16 wb_f2_hi [LNUM*D*FFD], wb_f2_lo [LNUM*D*FFD];
__device__ __nv_bfloat16 wb_g1_hi [LNUM*D3*D2], wb_g1_lo [LNUM*D3*D2];
__device__ __nv_bfloat16 wb_g2_hi [LNUM*D3*D2], wb_g2_lo [LNUM*D3*D2];

// ---------------- PTX helpers (portable: sm_80-level, no 'a' features) -------
__device__ __forceinline__ uint32_t smem_u32(const void* p) {
    uint32_t a;
    asm("{ .reg .u64 t; cvta.to.shared.u64 t, %1; cvt.u32.u64 %0, t; }" : "=r"(a) : "l"(p));
    return a;
}
__device__ __forceinline__ void cp16(uint32_t d, const void* g) {
    asm volatile("cp.async.cg.shared.global [%0], [%1], 16;" :: "r"(d), "l"(g));
}
__device__ __forceinline__ void ldm_x4(uint32_t* f, uint32_t addr) {
    asm volatile("ldmatrix.sync.aligned.m8n8.x4.shared.b16 {%0,%1,%2,%3}, [%4];"
                 : "=r"(f[0]), "=r"(f[1]), "=r"(f[2]), "=r"(f[3]) : "r"(addr));
}
__device__ __forceinline__ void mma16816(float* c, const uint32_t* a, uint32_t b0, uint32_t b1) {
    asm volatile(
        "mma.sync.aligned.m16n8k16.row.col.f32.bf16.bf16.f32 "
        "{%0,%1,%2,%3}, {%4,%5,%6,%7}, {%8,%9}, {%0,%1,%2,%3};"
        : "+f"(c[0]), "+f"(c[1]), "+f"(c[2]), "+f"(c[3])
        : "r"(a[0]), "r"(a[1]), "r"(a[2]), "r"(a[3]), "r"(b0), "r"(b1));
}

__device__ __forceinline__ float gelu_exact(float v) { return v * normcdff(v); }

// ---------------- bf16 hi/lo split GEMM via mma.sync ------------------------
#define SMEM_STAGE 32768      // 16KB A + 16KB B
#define SMEM_BYTES (2*SMEM_STAGE)

__global__ __launch_bounds__(256)
void gemm_mma(const __nv_bfloat16* __restrict__ Ahi, const __nv_bfloat16* __restrict__ Alo,
              const __nv_bfloat16* __restrict__ Whi, const __nv_bfloat16* __restrict__ Wlo,
              const float* __restrict__ bias,
              float* __restrict__ Cf,
              __nv_bfloat16* __restrict__ Chi, __nv_bfloat16* __restrict__ Clo,
              int ncols, int K, int mode)
{
    extern __shared__ char smem[];
    const uint32_t sb = smem_u32(smem);
    const int tid  = threadIdx.x;
    const int wid  = tid >> 5;
    const int lane = tid & 31;
    const int wm   = wid >> 1;
    const int wn   = wid & 1;
    const int row0 = blockIdx.y * 128;
    const int col0 = blockIdx.x * 128;

    float acc[2][8][4];
#pragma unroll
    for (int i = 0; i < 2; i++)
#pragma unroll
        for (int g = 0; g < 8; g++)
#pragma unroll
            for (int q = 0; q < 4; q++) acc[i][g][q] = 0.f;

    const int lr   = lane & 15;
    const int koff = (lane >> 4) << 4;
    uint32_t roffA[2], rxA[2], roffB[4], rxB[4];
#pragma unroll
    for (int i = 0; i < 2; i++) {
        int r = wm * 32 + i * 16 + lr;
        roffA[i] = r * 128; rxA[i] = (r & 7) << 4;
    }
#pragma unroll
    for (int j = 0; j < 4; j++) {
        int r = wn * 64 + j * 16 + lr;
        roffB[j] = r * 128; rxB[j] = (r & 7) << 4;
    }

    const int cpk = K / 64;
    const int nch = 3 * cpk;

    auto issue = [&](int cc, int stage) {
        const int seg = cc / cpk;
        const int kbase = (cc % cpk) * 64;
        const __nv_bfloat16* A = (seg == 2) ? Alo : Ahi;
        const __nv_bfloat16* W = (seg == 1) ? Wlo : Whi;
        const uint32_t sA = sb + stage * SMEM_STAGE;
        const uint32_t sB = sA + 16384;
#pragma unroll
        for (int i = 0; i < 4; i++) {
            int idx = tid + i * 256;
            int r = idx >> 3, c = idx & 7;
            uint32_t off = SWZ((uint32_t)(r * 128 + c * 16));
            cp16(sA + off, A + (size_t)(row0 + r) * K + kbase + c * 8);
            cp16(sB + off, W + (size_t)(col0 + r) * K + kbase + c * 8);
        }
        asm volatile("cp.async.commit_group;");
    };

    issue(0, 0);
    for (int cc = 0; cc < nch; cc++) {
        const int stage = cc & 1;
        asm volatile("cp.async.wait_group 0;");
        __syncthreads();
        if (cc + 1 < nch) issue(cc + 1, stage ^ 1);

        const uint32_t sA = sb + stage * SMEM_STAGE;
        const uint32_t sB = sA + 16384;
#pragma unroll
        for (int ks = 0; ks < 4; ks++) {
            const uint32_t kb = ks * 32 + koff;
            uint32_t a[2][4];
#pragma unroll
            for (int i = 0; i < 2; i++)
                ldm_x4(a[i], sA + roffA[i] + (kb ^ rxA[i]));
#pragma unroll
            for (int j = 0; j < 4; j++) {
                uint32_t b[4];
                ldm_x4(b, sB + roffB[j] + (kb ^ rxB[j]));
#pragma unroll
                for (int i = 0; i < 2; i++) {
                    mma16816(acc[i][j*2+0], a[i], b[0], b[2]);
                    mma16816(acc[i][j*2+1], a[i], b[1], b[3]);
                }
            }
        }
        __syncthreads();
    }

    const int rbase = row0 + wm * 32 + (lane >> 2);
    const int cbase = col0 + wn * 64 + (lane & 3) * 2;
#pragma unroll
    for (int i = 0; i < 2; i++) {
#pragma unroll
        for (int g = 0; g < 8; g++) {
            const int c = cbase + g * 8;
            const int r0 = rbase + i * 16;
            float b0 = bias ? bias[c]     : 0.f;
            float b1 = bias ? bias[c + 1] : 0.f;
            float v00 = acc[i][g][0] + b0, v01 = acc[i][g][1] + b1;
            float v10 = acc[i][g][2] + b0, v11 = acc[i][g][3] + b1;
            if (mode == 0) {
                *(float2*)(Cf + (size_t)r0 * ncols + c)       = make_float2(v00, v01);
                *(float2*)(Cf + (size_t)(r0+8) * ncols + c)   = make_float2(v10, v11);
            } else {
                v00 = gelu_exact(v00); v01 = gelu_exact(v01);
                v10 = gelu_exact(v10); v11 = gelu_exact(v11);
                __nv_bfloat16 h00 = __float2bfloat16(v00), h01 = __float2bfloat16(v01);
                __nv_bfloat16 h10 = __float2bfloat16(v10), h11 = __float2bfloat16(v11);
                __nv_bfloat16 l00 = __float2bfloat16(v00 - __bfloat162float(h00));
                __nv_bfloat16 l01 = __float2bfloat16(v01 - __bfloat162float(h01));
                __nv_bfloat16 l10 = __float2bfloat16(v10 - __bfloat162float(h10));
                __nv_bfloat16 l11 = __float2bfloat16(v11 - __bfloat162float(h11));
                *(__nv_bfloat162*)(Chi + (size_t)r0 * ncols + c)     = __halves2bfloat162(h00, h01);
                *(__nv_bfloat162*)(Chi + (size_t)(r0+8) * ncols + c) = __halves2bfloat162(h10, h11);
                *(__nv_bfloat162*)(Clo + (size_t)r0 * ncols + c)     = __halves2bfloat162(l00, l01);
                *(__nv_bfloat162*)(Clo + (size_t)(r0+8) * ncols + c) = __halves2bfloat162(l10, l11);
            }
        }
    }
}

// ---------------- flash-style tiled attention (fp32) ------------------------
// grid (TT/128, BATCH*H), 256 threads. CTA = 128 queries of one (b,h).
// K/V staged in smem 64 keys at a time; online softmax; acc in registers.
#define QTILE 128
#define KTILE 64
#define QP 68
#define KP 65
#define VP 68
#define SP 68
// f32 offsets in dynamic smem
#define AQ_OFF 0                 // Qs[128][QP]
#define AK_OFF (AQ_OFF + 128*QP) // Kt[64][KP]   (transposed: Kt[d][s])
#define AV_OFF (AK_OFF + 64*KP)  // Vs[64][VP]
#define AS_OFF (AV_OFF + 64*VP)  // Ss[128][SP]
#define AM_OFF (AS_OFF + 128*SP) // Mm[128]
#define AL_OFF (AM_OFF + 128)    // Ll[128]
#define AF_OFF (AL_OFF + 128)    // Fs[128]
#define AR_OFF (AF_OFF + 128)    // Red[128][2]
#define ATTN_SMEM ((AR_OFF + 256) * 4)

__global__ __launch_bounds__(256)
void attn_flash(const float* __restrict__ qkv, float* __restrict__ a) {
    extern __shared__ float sm[];
    float* Qs = sm + AQ_OFF;
    float* Kt = sm + AK_OFF;
    float* Vs = sm + AV_OFF;
    float* Ss = sm + AS_OFF;
    float* Mm = sm + AM_OFF;
    float* Ll = sm + AL_OFF;
    float* Fs = sm + AF_OFF;
    float* Red = sm + AR_OFF;

    const int tid = threadIdx.x;
    const int tx = tid & 15, ty = tid >> 4;
    const int bh = blockIdx.y;
    const int b  = bh >> 4;       // H == 16
    const int h  = bh & 15;
    const int q0 = blockIdx.x * QTILE;

    // load Q tile (pre-scaled)
#pragma unroll
    for (int i = 0; i < 8; i++) {
        int idx = tid + i * 256;
        int r = idx >> 4, c = idx & 15;
        float4 v = *(const float4*)(qkv + ((size_t)((q0 + r) * BATCH + b)) * D3 + h * DKH + c * 4);
        v.x *= ATT_SCALE; v.y *= ATT_SCALE; v.z *= ATT_SCALE; v.w *= ATT_SCALE;
        *(float4*)(Qs + r * QP + c * 4) = v;
    }
    if (tid < 128) { Mm[tid] = -1e30f; Ll[tid] = 0.f; }

    float acc[8][4];
#pragma unroll
    for (int i = 0; i < 8; i++)
#pragma unroll
        for (int j = 0; j < 4; j++) acc[i][j] = 0.f;

    __syncthreads();

    const int ntiles = blockIdx.x * 2 + 2;
    const int qred = tid >> 1, hf = tid & 1;     // reduction mapping

    for (int kt = 0; kt < ntiles; kt++) {
        const int s0 = kt * KTILE;
        // load K (transposed) and V tiles
#pragma unroll
        for (int i = 0; i < 4; i++) {
            int idx = tid + i * 256;
            int r = idx >> 4, c = idx & 15;
            const float* base = qkv + ((size_t)((s0 + r) * BATCH + b)) * D3 + h * DKH + c * 4;
            float4 kv = *(const float4*)(base + D);
            float4 vv = *(const float4*)(base + 2 * D);
            Kt[(c*4+0) * KP + r] = kv.x;
            Kt[(c*4+1) * KP + r] = kv.y;
            Kt[(c*4+2) * KP + r] = kv.z;
            Kt[(c*4+3) * KP + r] = kv.w;
            *(float4*)(Vs + r * VP + c * 4) = vv;
        }
        __syncthreads();

        // scores: 8 q-rows x 4 keys per thread
        float sreg[8][4];
#pragma unroll
        for (int i = 0; i < 8; i++)
#pragma unroll
            for (int j = 0; j < 4; j++) sreg[i][j] = 0.f;
#pragma unroll 8
        for (int d = 0; d < 64; d++) {
            float kq[4];
#pragma unroll
            for (int j = 0; j < 4; j++) kq[j] = Kt[d * KP + tx * 4 + j];
#pragma unroll
            for (int i = 0; i < 8; i++) {
                float qv = Qs[(ty * 8 + i) * QP + d];
#pragma unroll
                for (int j = 0; j < 4; j++) sreg[i][j] += qv * kq[j];
            }
        }
        // causal mask + store tile
#pragma unroll
        for (int i = 0; i < 8; i++) {
            const int qg = q0 + ty * 8 + i;
            float4 o;
            o.x = (s0 + tx*4 + 0 > qg) ? -1e30f : sreg[i][0];
            o.y = (s0 + tx*4 + 1 > qg) ? -1e30f : sreg[i][1];
            o.z = (s0 + tx*4 + 2 > qg) ? -1e30f : sreg[i][2];
            o.w = (s0 + tx*4 + 3 > qg) ? -1e30f : sreg[i][3];
            *(float4*)(Ss + (ty * 8 + i) * SP + tx * 4) = o;
        }
        __syncthreads();

        // row max (tile)
        {
            float mx = -1e30f;
            const float* row = Ss + qred * SP + hf * 32;
#pragma unroll 8
            for (int j = 0; j < 32; j++) mx = fmaxf(mx, row[j]);
            Red[qred * 2 + hf] = mx;
        }
        __syncthreads();
        if (hf == 0) {
            float tm = fmaxf(Red[qred * 2], Red[qred * 2 + 1]);
            float mo = Mm[qred];
            float mn = fmaxf(mo, tm);
            Mm[qred] = mn;
            Fs[qred] = __expf(mo - mn);
        }
        __syncthreads();
        // p = exp(s - m), partial sums
        {
            const float mq = Mm[qred];
            float* row = Ss + qred * SP + hf * 32;
            float sum = 0.f;
#pragma unroll 8
            for (int j = 0; j < 32; j++) {
                float e = __expf(row[j] - mq);
                row[j] = e; sum += e;
            }
            Red[qred * 2 + hf] = sum;
        }
        __syncthreads();
        if (hf == 0)
            Ll[qred] = Ll[qred] * Fs[qred] + Red[qred * 2] + Red[qred * 2 + 1];

        // rescale acc and accumulate P @ V
#pragma unroll
        for (int i = 0; i < 8; i++) {
            const float f = Fs[ty * 8 + i];
#pragma unroll
            for (int j = 0; j < 4; j++) acc[i][j] *= f;
        }
#pragma unroll 4
        for (int s = 0; s < 64; s++) {
            float v4[4];
#pragma unroll
            for (int j = 0; j < 4; j++) v4[j] = Vs[s * VP + tx * 4 + j];
#pragma unroll
            for (int i = 0; i < 8; i++) {
                const float p = Ss[(ty * 8 + i) * SP + s];
#pragma unroll
                for (int j = 0; j < 4; j++) acc[i][j] += p * v4[j];
            }
        }
        __syncthreads();
    }

    // write output
#pragma unroll
    for (int i = 0; i < 8; i++) {
        const int q = ty * 8 + i;
        const float inv = 1.f / Ll[q];
        float4 o;
        o.x = acc[i][0] * inv; o.y = acc[i][1] * inv;
        o.z = acc[i][2] * inv; o.w = acc[i][3] * inv;
        *(float4*)(a + ((size_t)((q0 + q) * BATCH + b)) * D + h * DKH + tx * 4) = o;
    }
}

// ---------------- layernorm -> hi/lo bf16 split ----------------
__global__ __launch_bounds__(256)
void ln_split(const float* __restrict__ x, const float* __restrict__ g,
              const float* __restrict__ b,
              __nv_bfloat16* __restrict__ hi, __nv_bfloat16* __restrict__ lo) {
    const int n = blockIdx.x;
    const float* xr = x + (size_t)n * D;
    const int tid = threadIdx.x;

    float s = 0.f, sq = 0.f;
    for (int j = tid; j < D; j += 256) { float v = xr[j]; s += v; sq += v * v; }
    __shared__ float rs[256], rq[256];
    rs[tid] = s; rq[tid] = sq; __syncthreads();
    for (int off = 128; off > 0; off >>= 1) {
        if (tid < off) { rs[tid] += rs[tid + off]; rq[tid] += rq[tid + off]; }
        __syncthreads();
    }
    const float mu  = rs[0] * (1.f / D);
    const float var = rq[0] * (1.f / D) - mu * mu;
    const float inv = rsqrtf(var + 1e-6f);

    for (int j = tid; j < D; j += 256) {
        float v = (xr[j] - mu) * inv * g[j] + b[j];
        __nv_bfloat16 h = __float2bfloat16(v);
        hi[(size_t)n * D + j] = h;
        lo[(size_t)n * D + j] = __float2bfloat16(v - __bfloat162float(h));
    }
}

// ---------------- plain f32 layernorm (final output) ----------------
__global__ __launch_bounds__(256)
void ln_kernel(const float* __restrict__ x, const float* __restrict__ g,
               const float* __restrict__ b, float* __restrict__ out) {
    const int n = blockIdx.x;
    const float* xr = x + (size_t)n * D;
    const int tid = threadIdx.x;

    float s = 0.f, sq = 0.f;
    for (int j = tid; j < D; j += 256) { float v = xr[j]; s += v; sq += v * v; }
    __shared__ float rs[256], rq[256];
    rs[tid] = s; rq[tid] = sq; __syncthreads();
    for (int off = 128; off > 0; off >>= 1) {
        if (tid < off) { rs[tid] += rs[tid + off]; rq[tid] += rq[tid + off]; }
        __syncthreads();
    }
    const float mu  = rs[0] * (1.f / D);
    const float var = rq[0] * (1.f / D) - mu * mu;
    const float inv = rsqrtf(var + 1e-6f);

    float* orow = out + (size_t)n * D;
    for (int j = tid; j < D; j += 256)
        orow[j] = (xr[j] - mu) * inv * g[j] + b[j];
}

// ---------------- elementwise kernels ----------------
__global__ void gelu_pe_kernel(float* __restrict__ x, const float* __restrict__ pe) {
    int idx = blockIdx.x * blockDim.x + threadIdx.x;
    if (idx >= NTOK * D) return;
    int t = idx / (BATCH * D);
    int d = idx % D;
    x[idx] = gelu_exact(x[idx]) + pe[t * D + d];
}

__global__ void gru_kernel(float* __restrict__ x, const float* __restrict__ gate,
                           const float* __restrict__ bg) {
    int idx = blockIdx.x * blockDim.x + threadIdx.x;
    if (idx >= NTOK * D) return;
    int n = idx / D;
    int j = idx % D;
    const float* grow = gate + (size_t)n * D3;
    float gr = grow[j];
    float gz = grow[D + j];
    float gh = grow[2 * D + j];
    float r = 1.f / (1.f + expf(-gr));
    float z = 1.f / (1.f + expf(-(gz - bg[j])));
    float hh = tanhf(gh * r);
    float xv = x[idx];
    x[idx] = (1.f - z) * xv + z * hh;
}

__global__ void cvt_split4(const float4* __restrict__ x,
                           __nv_bfloat162* __restrict__ hi, __nv_bfloat162* __restrict__ lo,
                           int n4) {
    int i = blockIdx.x * blockDim.x + threadIdx.x;
    if (i >= n4) return;
    float4 v = x[i];
    __nv_bfloat16 h0 = __float2bfloat16(v.x), h1 = __float2bfloat16(v.y);
    __nv_bfloat16 h2 = __float2bfloat16(v.z), h3 = __float2bfloat16(v.w);
    __nv_bfloat16 l0 = __float2bfloat16(v.x - __bfloat162float(h0));
    __nv_bfloat16 l1 = __float2bfloat16(v.y - __bfloat162float(h1));
    __nv_bfloat16 l2 = __float2bfloat16(v.z - __bfloat162float(h2));
    __nv_bfloat16 l3 = __float2bfloat16(v.w - __bfloat162float(h3));
    hi[2*i]   = __halves2bfloat162(h0, h1);
    hi[2*i+1] = __halves2bfloat162(h2, h3);
    lo[2*i]   = __halves2bfloat162(l0, l1);
    lo[2*i+1] = __halves2bfloat162(l2, l3);
}

__global__ void cvt_concat4(const float* __restrict__ x, const float* __restrict__ y,
                            __nv_bfloat162* __restrict__ hi, __nv_bfloat162* __restrict__ lo) {
    int i = blockIdx.x * blockDim.x + threadIdx.x;
    if (i >= NTOK * D2 / 4) return;
    int e = i * 4;
    int n = e / D2;
    int j = e % D2;
    const float* src = (j < D) ? (x + (size_t)n * D + j) : (y + (size_t)n * D + (j - D));
    float4 v = *(const float4*)src;
    __nv_bfloat16 h0 = __float2bfloat16(v.x), h1 = __float2bfloat16(v.y);
    __nv_bfloat16 h2 = __float2bfloat16(v.z), h3 = __float2bfloat16(v.w);
    __nv_bfloat16 l0 = __float2bfloat16(v.x - __bfloat162float(h0));
    __nv_bfloat16 l1 = __float2bfloat16(v.y - __bfloat162float(h1));
    __nv_bfloat16 l2 = __float2bfloat16(v.z - __bfloat162float(h2));
    __nv_bfloat16 l3 = __float2bfloat16(v.w - __bfloat162float(h3));
    hi[2*i]   = __halves2bfloat162(h0, h1);
    hi[2*i+1] = __halves2bfloat162(h2, h3);
    lo[2*i]   = __halves2bfloat162(l0, l1);
    lo[2*i+1] = __halves2bfloat162(l2, l3);
}

// ---------------- driver ----------------
extern "C" void kernel_launch(void* const* d_in, const int* in_sizes, int n_in,
                              void* d_out, int out_size) {
    const float* x_in  = (const float*)d_in[0];
    const float* pe    = (const float*)d_in[1];
    const float* in_w  = (const float*)d_in[2];
    const float* in_b  = (const float*)d_in[3];
    const float* qkv_w = (const float*)d_in[4];
    const float* out_w = (const float*)d_in[5];
    const float* out_b = (const float*)d_in[6];
    const float* ln1_g = (const float*)d_in[7];
    const float* ln1_b = (const float*)d_in[8];
    const float* ln2_g = (const float*)d_in[9];
    const float* ln2_b = (const float*)d_in[10];
    const float* ff_w1 = (const float*)d_in[11];
    const float* ff_b1 = (const float*)d_in[12];
    const float* ff_w2 = (const float*)d_in[13];
    const float* ff_b2 = (const float*)d_in[14];
    const float* g1_w  = (const float*)d_in[15];
    const float* g1_bg = (const float*)d_in[16];
    const float* g2_w  = (const float*)d_in[17];
    const float* g2_bg = (const float*)d_in[18];
    const float* on_g  = (const float*)d_in[19];
    const float* on_b  = (const float*)d_in[20];

    float *px, *pqkv, *pa, *pproj, *pgate;
    __nv_bfloat16 *ahi, *alo, *fhi, *flo;
    __nv_bfloat16 *w_in_h, *w_in_l, *w_qkv_h, *w_qkv_l, *w_out_h, *w_out_l;
    __nv_bfloat16 *w_f1_h, *w_f1_l, *w_f2_h, *w_f2_l, *w_g1_h, *w_g1_l, *w_g2_h, *w_g2_l;
    cudaGetSymbolAddress((void**)&px,    g_x);
    cudaGetSymbolAddress((void**)&pqkv,  g_qkv);
    cudaGetSymbolAddress((void**)&pa,    g_a);
    cudaGetSymbolAddress((void**)&pproj, g_proj);
    cudaGetSymbolAddress((void**)&pgate, g_gate);
    cudaGetSymbolAddress((void**)&ahi,   g_ahi);
    cudaGetSymbolAddress((void**)&alo,   g_alo);
    cudaGetSymbolAddress((void**)&fhi,   g_fhi);
    cudaGetSymbolAddress((void**)&flo,   g_flo);
    cudaGetSymbolAddress((void**)&w_in_h,  wb_in_hi);  cudaGetSymbolAddress((void**)&w_in_l,  wb_in_lo);
    cudaGetSymbolAddress((void**)&w_qkv_h, wb_qkv_hi); cudaGetSymbolAddress((void**)&w_qkv_l, wb_qkv_lo);
    cudaGetSymbolAddress((void**)&w_out_h, wb_out_hi); cudaGetSymbolAddress((void**)&w_out_l, wb_out_lo);
    cudaGetSymbolAddress((void**)&w_f1_h,  wb_f1_hi);  cudaGetSymbolAddress((void**)&w_f1_l,  wb_f1_lo);
    cudaGetSymbolAddress((void**)&w_f2_h,  wb_f2_hi);  cudaGetSymbolAddress((void**)&w_f2_l,  wb_f2_lo);
    cudaGetSymbolAddress((void**)&w_g1_h,  wb_g1_hi);  cudaGetSymbolAddress((void**)&w_g1_l,  wb_g1_lo);
    cudaGetSymbolAddress((void**)&w_g2_h,  wb_g2_hi);  cudaGetSymbolAddress((void**)&w_g2_l,  wb_g2_lo);

    cudaFuncSetAttribute(gemm_mma, cudaFuncAttributeMaxDynamicSharedMemorySize, SMEM_BYTES);
    cudaFuncSetAttribute(attn_flash, cudaFuncAttributeMaxDynamicSharedMemorySize, ATTN_SMEM);

    const int EW = 256;
    auto cvtgrid = [](int n) { return (n / 4 + 255) / 256; };

    // ---- weight hi/lo splits ----
    cvt_split4<<<cvtgrid(D*D),        EW>>>((const float4*)in_w,  (__nv_bfloat162*)w_in_h,  (__nv_bfloat162*)w_in_l,  D*D/4);
    cvt_split4<<<cvtgrid(LNUM*D3*D),  EW>>>((const float4*)qkv_w, (__nv_bfloat162*)w_qkv_h, (__nv_bfloat162*)w_qkv_l, LNUM*D3*D/4);
    cvt_split4<<<cvtgrid(LNUM*D*D),   EW>>>((const float4*)out_w, (__nv_bfloat162*)w_out_h, (__nv_bfloat162*)w_out_l, LNUM*D*D/4);
    cvt_split4<<<cvtgrid(LNUM*FFD*D), EW>>>((const float4*)ff_w1, (__nv_bfloat162*)w_f1_h,  (__nv_bfloat162*)w_f1_l,  LNUM*FFD*D/4);
    cvt_split4<<<cvtgrid(LNUM*D*FFD), EW>>>((const float4*)ff_w2, (__nv_bfloat162*)w_f2_h,  (__nv_bfloat162*)w_f2_l,  LNUM*D*FFD/4);
    cvt_split4<<<cvtgrid(LNUM*D3*D2), EW>>>((const float4*)g1_w,  (__nv_bfloat162*)w_g1_h,  (__nv_bfloat162*)w_g1_l,  LNUM*D3*D2/4);
    cvt_split4<<<cvtgrid(LNUM*D3*D2), EW>>>((const float4*)g2_w,  (__nv_bfloat162*)w_g2_h,  (__nv_bfloat162*)w_g2_l,  LNUM*D3*D2/4);

    dim3 gD  (D/128,   NTOK/128);
    dim3 gD3 (D3/128,  NTOK/128);
    dim3 gFF (FFD/128, NTOK/128);

    // ---- input projection + GELU + positional encoding ----
    cvt_split4<<<cvtgrid(NTOK*D), EW>>>((const float4*)x_in, (__nv_bfloat162*)ahi, (__nv_bfloat162*)alo, NTOK*D/4);
    gemm_mma<<<gD, 256, SMEM_BYTES>>>(ahi, alo, w_in_h, w_in_l, in_b, px, 0, 0, D, D, 0);
    gelu_pe_kernel<<<(NTOK*D + EW - 1)/EW, EW>>>(px, pe);

    for (int l = 0; l < LNUM; l++) {
        const __nv_bfloat16* qwh = w_qkv_h + (size_t)l*D3*D;  const __nv_bfloat16* qwl = w_qkv_l + (size_t)l*D3*D;
        const __nv_bfloat16* owh = w_out_h + (size_t)l*D*D;   const __nv_bfloat16* owl = w_out_l + (size_t)l*D*D;
        const __nv_bfloat16* f1h = w_f1_h  + (size_t)l*FFD*D; const __nv_bfloat16* f1l = w_f1_l  + (size_t)l*FFD*D;
        const __nv_bfloat16* f2h = w_f2_h  + (size_t)l*D*FFD; const __nv_bfloat16* f2l = w_f2_l  + (size_t)l*D*FFD;
        const __nv_bfloat16* g1h = w_g1_h  + (size_t)l*D3*D2; const __nv_bfloat16* g1l = w_g1_l  + (size_t)l*D3*D2;
        const __nv_bfloat16* g2h = w_g2_h  + (size_t)l*D3*D2; const __nv_bfloat16* g2l = w_g2_l  + (size_t)l*D3*D2;
        const float* ob  = out_b + (size_t)l*D;
        const float* l1g = ln1_g + (size_t)l*D;  const float* l1b = ln1_b + (size_t)l*D;
        const float* l2g = ln2_g + (size_t)l*D;  const float* l2b = ln2_b + (size_t)l*D;
        const float* fb1 = ff_b1 + (size_t)l*FFD;
        const float* fb2 = ff_b2 + (size_t)l*D;
        const float* gb1 = g1_bg + (size_t)l*D;
        const float* gb2 = g2_bg + (size_t)l*D;

        // attention block
        ln_split<<<NTOK, 256>>>(px, l1g, l1b, ahi, alo);
        gemm_mma<<<gD3, 256, SMEM_BYTES>>>(ahi, alo, qwh, qwl, nullptr, pqkv, 0, 0, D3, D, 0);
        attn_flash<<<dim3(TT/QTILE, BATCH*H), 256, ATTN_SMEM>>>(pqkv, pa);
        cvt_split4<<<cvtgrid(NTOK*D), EW>>>((const float4*)pa, (__nv_bfloat162*)ahi, (__nv_bfloat162*)alo, NTOK*D/4);
        gemm_mma<<<gD, 256, SMEM_BYTES>>>(ahi, alo, owh, owl, ob, pproj, 0, 0, D, D, 0);
        cvt_concat4<<<(NTOK*D2/4 + EW - 1)/EW, EW>>>(px, pproj, (__nv_bfloat162*)ahi, (__nv_bfloat162*)alo);
        gemm_mma<<<gD3, 256, SMEM_BYTES>>>(ahi, alo, g1h, g1l, nullptr, pgate, 0, 0, D3, D2, 0);
        gru_kernel<<<(NTOK*D + EW - 1)/EW, EW>>>(px, pgate, gb1);

        // feed-forward block
        ln_split<<<NTOK, 256>>>(px, l2g, l2b, ahi, alo);
        gemm_mma<<<gFF, 256, SMEM_BYTES>>>(ahi, alo, f1h, f1l, fb1, nullptr, fhi, flo, FFD, D, 1);
        gemm_mma<<<gD, 256, SMEM_BYTES>>>(fhi, flo, f2h, f2l, fb2, pproj, 0, 0, D, FFD, 0);
        cvt_concat4<<<(NTOK*D2/4 + EW - 1)/EW, EW>>>(px, pproj, (__nv_bfloat162*)ahi, (__nv_bfloat162*)alo);
        gemm_mma<<<gD3, 256, SMEM_BYTES>>>(ahi, alo, g2h, g2l, nullptr, pgate, 0, 0, D3, D2, 0);
        gru_kernel<<<(NTOK*D + EW - 1)/EW, EW>>>(px, pgate, gb2);
    }

    ln_kernel<<<NTOK, 256>>>(px, on_g, on_b, (float*)d_out);
}

// round 5
// speedup vs baseline: 3.2252x; 1.0641x over previous
#include <cuda_runtime.h>
#include <cuda_bf16.h>
#include <math.h>
#include <stdint.h>

// ---------------- problem constants ----------------
#define LNUM  6
#define D     1024
#define H     16
#define DKH   64
#define FFD   4096
#define TT    1024
#define BATCH 2
#define NTOK  2048
#define D3    3072
#define D2    2048
#define ATT_SCALE 0.125f

#define SWZ(o) ((o) ^ (((o) >> 3) & 0x70))

// ---------------- scratch (device globals; no allocs allowed) ----------------
__device__ float g_x   [NTOK*D];     // residual stream (f32)
__device__ float g_qkv [NTOK*D3];
__device__ float g_gate[NTOK*D3];
__device__ __nv_bfloat16 g_chi[NTOK*D2],  g_clo[NTOK*D2];   // concat [x,y] hi/lo
__device__ __nv_bfloat16 g_lhi[NTOK*D],   g_llo[NTOK*D];    // LN output hi/lo
__device__ __nv_bfloat16 g_phi[NTOK*D],   g_plo[NTOK*D];    // attn output hi/lo
__device__ __nv_bfloat16 g_fhi[NTOK*FFD], g_flo[NTOK*FFD];  // FF hidden hi/lo
__device__ __nv_bfloat16 g_xhi[NTOK*D],   g_xlo[NTOK*D];    // input x split
__device__ __nv_bfloat16 wb_in_hi [D*D],        wb_in_lo [D*D];
__device__ __nv_bfloat16 wb_qkv_hi[LNUM*D3*D],  wb_qkv_lo[LNUM*D3*D];
__device__ __nv_bfloat16 wb_out_hi[LNUM*D*D],   wb_out_lo[LNUM*D*D];
__device__ __nv_bfloat16 wb_f1_hi [LNUM*FFD*D], wb_f1_lo [LNUM*FFD*D];
__device__ __nv_bfloat16 wb_f2_hi [LNUM*D*FFD], wb_f2_lo [LNUM*D*FFD];
__device__ __nv_bfloat16 wb_g1_hi [LNUM*D3*D2], wb_g1_lo [LNUM*D3*D2];
__device__ __nv_bfloat16 wb_g2_hi [LNUM*D3*D2], wb_g2_lo [LNUM*D3*D2];

// ---------------- PTX helpers (portable: sm_80-level) ----------------
__device__ __forceinline__ uint32_t smem_u32(const void* p) {
    uint32_t a;
    asm("{ .reg .u64 t; cvta.to.shared.u64 t, %1; cvt.u32.u64 %0, t; }" : "=r"(a) : "l"(p));
    return a;
}
__device__ __forceinline__ void cp16(uint32_t d, const void* g) {
    asm volatile("cp.async.cg.shared.global [%0], [%1], 16;" :: "r"(d), "l"(g));
}
__device__ __forceinline__ void ldm_x4(uint32_t* f, uint32_t addr) {
    asm volatile("ldmatrix.sync.aligned.m8n8.x4.shared.b16 {%0,%1,%2,%3}, [%4];"
                 : "=r"(f[0]), "=r"(f[1]), "=r"(f[2]), "=r"(f[3]) : "r"(addr));
}
__device__ __forceinline__ void mma16816(float* c, const uint32_t* a, uint32_t b0, uint32_t b1) {
    asm volatile(
        "mma.sync.aligned.m16n8k16.row.col.f32.bf16.bf16.f32 "
        "{%0,%1,%2,%3}, {%4,%5,%6,%7}, {%8,%9}, {%0,%1,%2,%3};"
        : "+f"(c[0]), "+f"(c[1]), "+f"(c[2]), "+f"(c[3])
        : "r"(a[0]), "r"(a[1]), "r"(a[2]), "r"(a[3]), "r"(b0), "r"(b1));
}
__device__ __forceinline__ float gelu_exact(float v) { return v * normcdff(v); }
__device__ __forceinline__ void split_bf16(float v, __nv_bfloat16& h, __nv_bfloat16& l) {
    h = __float2bfloat16(v);
    l = __float2bfloat16(v - __bfloat162float(h));
}

// ---------------- bf16 hi/lo split GEMM v2 (4-tile stages) -------------------
// C[NTOK,ncols] = A[NTOK,K] @ W[ncols,K]^T (3-term hi/lo accumulation)
// Each k-chunk stages Ahi,Alo,Whi,Wlo (64KB), runs all 3 term passes.
// mode 0: Cf = result (+bias), leading dim ldc.
// mode 1: gelu(result+bias) -> hi/lo bf16 at ldc.
// mode 2: result+bias      -> hi/lo bf16 at ldc.
#define STAGE_B 65536
#define SMEM_BYTES (2*STAGE_B)

__global__ __launch_bounds__(256)
void gemm_mma(const __nv_bfloat16* __restrict__ Ahi, const __nv_bfloat16* __restrict__ Alo,
              int lda,
              const __nv_bfloat16* __restrict__ Whi, const __nv_bfloat16* __restrict__ Wlo,
              const float* __restrict__ bias,
              float* __restrict__ Cf,
              __nv_bfloat16* __restrict__ Chi, __nv_bfloat16* __restrict__ Clo,
              int ldc, int K, int mode)
{
    extern __shared__ char smem[];
    const uint32_t sb = smem_u32(smem);
    const int tid  = threadIdx.x;
    const int wid  = tid >> 5;
    const int lane = tid & 31;
    const int wm   = wid >> 1;
    const int wn   = wid & 1;
    const int row0 = blockIdx.y * 128;
    const int col0 = blockIdx.x * 128;

    float acc[2][8][4];
#pragma unroll
    for (int i = 0; i < 2; i++)
#pragma unroll
        for (int g = 0; g < 8; g++)
#pragma unroll
            for (int q = 0; q < 4; q++) acc[i][g][q] = 0.f;

    const int lr   = lane & 15;
    const int koff = (lane >> 4) << 4;
    uint32_t roffA[2], rxA[2], roffB[4], rxB[4];
#pragma unroll
    for (int i = 0; i < 2; i++) {
        int r = wm * 32 + i * 16 + lr;
        roffA[i] = r * 128; rxA[i] = (r & 7) << 4;
    }
#pragma unroll
    for (int j = 0; j < 4; j++) {
        int r = wn * 64 + j * 16 + lr;
        roffB[j] = r * 128; rxB[j] = (r & 7) << 4;
    }

    const int nch = K / 64;
    const int ldr = tid >> 3, ldc4 = tid & 7;                 // loader mapping
    const uint32_t ldoff = SWZ((uint32_t)(ldr * 128 + ldc4 * 16));

    auto issue = [&](int cc, int stage) {
        const int kbase = cc * 64;
        const uint32_t st = sb + stage * STAGE_B;
#pragma unroll
        for (int i = 0; i < 4; i++) {
            int r = ldr + i * 32;
            uint32_t off = SWZ((uint32_t)(r * 128 + ldc4 * 16));
            size_t sa = (size_t)(row0 + r) * lda + kbase + ldc4 * 8;
            size_t sw = (size_t)(col0 + r) * K   + kbase + ldc4 * 8;
            cp16(st +         off, Ahi + sa);
            cp16(st + 16384 + off, Alo + sa);
            cp16(st + 32768 + off, Whi + sw);
            cp16(st + 49152 + off, Wlo + sw);
        }
        asm volatile("cp.async.commit_group;");
    };
    (void)ldoff;

    issue(0, 0);
    for (int cc = 0; cc < nch; cc++) {
        const int stage = cc & 1;
        asm volatile("cp.async.wait_group 0;");
        __syncthreads();
        if (cc + 1 < nch) issue(cc + 1, stage ^ 1);

        const uint32_t AH = sb + stage * STAGE_B;
        const uint32_t AL = AH + 16384;
        const uint32_t WHs = AH + 32768;
        const uint32_t WLs = AH + 49152;
#pragma unroll
        for (int ks = 0; ks < 4; ks++) {
            const uint32_t kb = ks * 32 + koff;
            uint32_t ah[2][4], al[2][4];
#pragma unroll
            for (int i = 0; i < 2; i++) {
                ldm_x4(ah[i], AH + roffA[i] + (kb ^ rxA[i]));
                ldm_x4(al[i], AL + roffA[i] + (kb ^ rxA[i]));
            }
#pragma unroll
            for (int j = 0; j < 4; j++) {
                uint32_t bh[4], bl[4];
                ldm_x4(bh, WHs + roffB[j] + (kb ^ rxB[j]));
                ldm_x4(bl, WLs + roffB[j] + (kb ^ rxB[j]));
#pragma unroll
                for (int i = 0; i < 2; i++) {
                    mma16816(acc[i][j*2+0], ah[i], bh[0], bh[2]);
                    mma16816(acc[i][j*2+1], ah[i], bh[1], bh[3]);
                    mma16816(acc[i][j*2+0], ah[i], bl[0], bl[2]);
                    mma16816(acc[i][j*2+1], ah[i], bl[1], bl[3]);
                    mma16816(acc[i][j*2+0], al[i], bh[0], bh[2]);
                    mma16816(acc[i][j*2+1], al[i], bh[1], bh[3]);
                }
            }
        }
        __syncthreads();
    }

    const int rbase = row0 + wm * 32 + (lane >> 2);
    const int cbase = wn * 64 + (lane & 3) * 2;      // col within CTA tile
#pragma unroll
    for (int i = 0; i < 2; i++) {
#pragma unroll
        for (int g = 0; g < 8; g++) {
            const int c  = cbase + g * 8;            // 0..127
            const int cg = col0 + c;                 // global col (bias index)
            const int r0 = rbase + i * 16;
            float b0 = bias ? bias[cg]     : 0.f;
            float b1 = bias ? bias[cg + 1] : 0.f;
            float v00 = acc[i][g][0] + b0, v01 = acc[i][g][1] + b1;
            float v10 = acc[i][g][2] + b0, v11 = acc[i][g][3] + b1;
            if (mode == 0) {
                *(float2*)(Cf + (size_t)r0 * ldc + cg)     = make_float2(v00, v01);
                *(float2*)(Cf + (size_t)(r0+8) * ldc + cg) = make_float2(v10, v11);
            } else {
                if (mode == 1) {
                    v00 = gelu_exact(v00); v01 = gelu_exact(v01);
                    v10 = gelu_exact(v10); v11 = gelu_exact(v11);
                }
                __nv_bfloat16 h00, l00, h01, l01, h10, l10, h11, l11;
                split_bf16(v00, h00, l00); split_bf16(v01, h01, l01);
                split_bf16(v10, h10, l10); split_bf16(v11, h11, l11);
                *(__nv_bfloat162*)(Chi + (size_t)r0 * ldc + cg)     = __halves2bfloat162(h00, h01);
                *(__nv_bfloat162*)(Chi + (size_t)(r0+8) * ldc + cg) = __halves2bfloat162(h10, h11);
                *(__nv_bfloat162*)(Clo + (size_t)r0 * ldc + cg)     = __halves2bfloat162(l00, l01);
                *(__nv_bfloat162*)(Clo + (size_t)(r0+8) * ldc + cg) = __halves2bfloat162(l10, l11);
            }
        }
    }
}

// ---------------- flash-style tiled attention (fp32, hi/lo bf16 out) ---------
#define QTILE 128
#define KTILE 64
#define QP 68
#define KP 65
#define VP 68
#define SP 68
#define AQ_OFF 0
#define AK_OFF (AQ_OFF + 128*QP)
#define AV_OFF (AK_OFF + 64*KP)
#define AS_OFF (AV_OFF + 64*VP)
#define AM_OFF (AS_OFF + 128*SP)
#define AL_OFF (AM_OFF + 128)
#define AF_OFF (AL_OFF + 128)
#define AR_OFF (AF_OFF + 128)
#define ATTN_SMEM ((AR_OFF + 256) * 4)

__global__ __launch_bounds__(256)
void attn_flash(const float* __restrict__ qkv,
                __nv_bfloat16* __restrict__ ahi, __nv_bfloat16* __restrict__ alo) {
    extern __shared__ float sm[];
    float* Qs = sm + AQ_OFF;
    float* Kt = sm + AK_OFF;
    float* Vs = sm + AV_OFF;
    float* Ss = sm + AS_OFF;
    float* Mm = sm + AM_OFF;
    float* Ll = sm + AL_OFF;
    float* Fs = sm + AF_OFF;
    float* Red = sm + AR_OFF;

    const int tid = threadIdx.x;
    const int tx = tid & 15, ty = tid >> 4;
    const int bh = blockIdx.y;
    const int b  = bh >> 4;
    const int h  = bh & 15;
    const int q0 = blockIdx.x * QTILE;

#pragma unroll
    for (int i = 0; i < 8; i++) {
        int idx = tid + i * 256;
        int r = idx >> 4, c = idx & 15;
        float4 v = *(const float4*)(qkv + ((size_t)((q0 + r) * BATCH + b)) * D3 + h * DKH + c * 4);
        v.x *= ATT_SCALE; v.y *= ATT_SCALE; v.z *= ATT_SCALE; v.w *= ATT_SCALE;
        *(float4*)(Qs + r * QP + c * 4) = v;
    }
    if (tid < 128) { Mm[tid] = -1e30f; Ll[tid] = 0.f; }

    float acc[8][4];
#pragma unroll
    for (int i = 0; i < 8; i++)
#pragma unroll
        for (int j = 0; j < 4; j++) acc[i][j] = 0.f;

    __syncthreads();

    const int ntiles = blockIdx.x * 2 + 2;
    const int qred = tid >> 1, hf = tid & 1;

    for (int kt = 0; kt < ntiles; kt++) {
        const int s0 = kt * KTILE;
#pragma unroll
        for (int i = 0; i < 4; i++) {
            int idx = tid + i * 256;
            int r = idx >> 4, c = idx & 15;
            const float* base = qkv + ((size_t)((s0 + r) * BATCH + b)) * D3 + h * DKH + c * 4;
            float4 kv = *(const float4*)(base + D);
            float4 vv = *(const float4*)(base + 2 * D);
            Kt[(c*4+0) * KP + r] = kv.x;
            Kt[(c*4+1) * KP + r] = kv.y;
            Kt[(c*4+2) * KP + r] = kv.z;
            Kt[(c*4+3) * KP + r] = kv.w;
            *(float4*)(Vs + r * VP + c * 4) = vv;
        }
        __syncthreads();

        float sreg[8][4];
#pragma unroll
        for (int i = 0; i < 8; i++)
#pragma unroll
            for (int j = 0; j < 4; j++) sreg[i][j] = 0.f;
#pragma unroll 8
        for (int d = 0; d < 64; d++) {
            float kq[4];
#pragma unroll
            for (int j = 0; j < 4; j++) kq[j] = Kt[d * KP + tx * 4 + j];
#pragma unroll
            for (int i = 0; i < 8; i++) {
                float qv = Qs[(ty * 8 + i) * QP + d];
#pragma unroll
                for (int j = 0; j < 4; j++) sreg[i][j] += qv * kq[j];
            }
        }
#pragma unroll
        for (int i = 0; i < 8; i++) {
            const int qg = q0 + ty * 8 + i;
            float4 o;
            o.x = (s0 + tx*4 + 0 > qg) ? -1e30f : sreg[i][0];
            o.y = (s0 + tx*4 + 1 > qg) ? -1e30f : sreg[i][1];
            o.z = (s0 + tx*4 + 2 > qg) ? -1e30f : sreg[i][2];
            o.w = (s0 + tx*4 + 3 > qg) ? -1e30f : sreg[i][3];
            *(float4*)(Ss + (ty * 8 + i) * SP + tx * 4) = o;
        }
        __syncthreads();

        {
            float mx = -1e30f;
            const float* row = Ss + qred * SP + hf * 32;
#pragma unroll 8
            for (int j = 0; j < 32; j++) mx = fmaxf(mx, row[j]);
            Red[qred * 2 + hf] = mx;
        }
        __syncthreads();
        if (hf == 0) {
            float tm = fmaxf(Red[qred * 2], Red[qred * 2 + 1]);
            float mo = Mm[qred];
            float mn = fmaxf(mo, tm);
            Mm[qred] = mn;
            Fs[qred] = __expf(mo - mn);
        }
        __syncthreads();
        {
            const float mq = Mm[qred];
            float* row = Ss + qred * SP + hf * 32;
            float sum = 0.f;
#pragma unroll 8
            for (int j = 0; j < 32; j++) {
                float e = __expf(row[j] - mq);
                row[j] = e; sum += e;
            }
            Red[qred * 2 + hf] = sum;
        }
        __syncthreads();
        if (hf == 0)
            Ll[qred] = Ll[qred] * Fs[qred] + Red[qred * 2] + Red[qred * 2 + 1];

#pragma unroll
        for (int i = 0; i < 8; i++) {
            const float f = Fs[ty * 8 + i];
#pragma unroll
            for (int j = 0; j < 4; j++) acc[i][j] *= f;
        }
#pragma unroll 4
        for (int s = 0; s < 64; s++) {
            float v4[4];
#pragma unroll
            for (int j = 0; j < 4; j++) v4[j] = Vs[s * VP + tx * 4 + j];
#pragma unroll
            for (int i = 0; i < 8; i++) {
                const float p = Ss[(ty * 8 + i) * SP + s];
#pragma unroll
                for (int j = 0; j < 4; j++) acc[i][j] += p * v4[j];
            }
        }
        __syncthreads();
    }

#pragma unroll
    for (int i = 0; i < 8; i++) {
        const int q = ty * 8 + i;
        const float inv = 1.f / Ll[q];
        float v0 = acc[i][0] * inv, v1 = acc[i][1] * inv;
        float v2 = acc[i][2] * inv, v3 = acc[i][3] * inv;
        __nv_bfloat16 h0, l0, h1, l1, h2, l2, h3, l3;
        split_bf16(v0, h0, l0); split_bf16(v1, h1, l1);
        split_bf16(v2, h2, l2); split_bf16(v3, h3, l3);
        size_t base = ((size_t)((q0 + q) * BATCH + b)) * D + h * DKH + tx * 4;
        *(__nv_bfloat162*)(ahi + base)     = __halves2bfloat162(h0, h1);
        *(__nv_bfloat162*)(ahi + base + 2) = __halves2bfloat162(h2, h3);
        *(__nv_bfloat162*)(alo + base)     = __halves2bfloat162(l0, l1);
        *(__nv_bfloat162*)(alo + base + 2) = __halves2bfloat162(l2, l3);
    }
}

// ---------------- fused GRU + LN + splits (one block per token) --------------
// x_new = gru(x, gate); px <- x_new; cat-left <- split(x_new);
// y = LN(x_new; g,b); if outf: outf <- y (f32) else lnhi/lnlo <- split(y).
__global__ __launch_bounds__(256)
void gru_ln_split(float* __restrict__ px, const float* __restrict__ gate,
                  const float* __restrict__ bg,
                  const float* __restrict__ g, const float* __restrict__ b,
                  __nv_bfloat16* __restrict__ cathi, __nv_bfloat16* __restrict__ catlo,
                  __nv_bfloat16* __restrict__ lnhi, __nv_bfloat16* __restrict__ lnlo,
                  float* __restrict__ outf) {
    const int n = blockIdx.x;
    const int tid = threadIdx.x;
    const float* grow = gate + (size_t)n * D3;
    float vals[4];
    float s = 0.f, sq = 0.f;
#pragma unroll
    for (int k = 0; k < 4; k++) {
        const int j = tid + k * 256;
        float gr = grow[j];
        float gz = grow[D + j];
        float gh = grow[2 * D + j];
        float r = 1.f / (1.f + __expf(-gr));
        float z = 1.f / (1.f + __expf(-(gz - bg[j])));
        float hh = tanhf(gh * r);
        float xv = px[(size_t)n * D + j];
        float v = (1.f - z) * xv + z * hh;
        px[(size_t)n * D + j] = v;
        vals[k] = v;
        __nv_bfloat16 h, l; split_bf16(v, h, l);
        cathi[(size_t)n * D2 + j] = h;
        catlo[(size_t)n * D2 + j] = l;
        s += v; sq += v * v;
    }
    __shared__ float rs[256], rq[256];
    rs[tid] = s; rq[tid] = sq; __syncthreads();
    for (int off = 128; off > 0; off >>= 1) {
        if (tid < off) { rs[tid] += rs[tid + off]; rq[tid] += rq[tid + off]; }
        __syncthreads();
    }
    const float mu  = rs[0] * (1.f / D);
    const float var = rq[0] * (1.f / D) - mu * mu;
    const float inv = rsqrtf(var + 1e-6f);
#pragma unroll
    for (int k = 0; k < 4; k++) {
        const int j = tid + k * 256;
        float y = (vals[k] - mu) * inv * g[j] + b[j];
        if (outf) {
            outf[(size_t)n * D + j] = y;
        } else {
            __nv_bfloat16 h, l; split_bf16(y, h, l);
            lnhi[(size_t)n * D + j] = h;
            lnlo[(size_t)n * D + j] = l;
        }
    }
}

// ---------------- fused GELU+PE + LN + splits (layer-0 entry) ----------------
__global__ __launch_bounds__(256)
void gelu_pe_ln_split(float* __restrict__ px, const float* __restrict__ pe,
                      const float* __restrict__ g, const float* __restrict__ b,
                      __nv_bfloat16* __restrict__ cathi, __nv_bfloat16* __restrict__ catlo,
                      __nv_bfloat16* __restrict__ lnhi, __nv_bfloat16* __restrict__ lnlo) {
    const int n = blockIdx.x;
    const int t = n >> 1;           // BATCH == 2
    const int tid = threadIdx.x;
    float vals[4];
    float s = 0.f, sq = 0.f;
#pragma unroll
    for (int k = 0; k < 4; k++) {
        const int j = tid + k * 256;
        float v = gelu_exact(px[(size_t)n * D + j]) + pe[(size_t)t * D + j];
        px[(size_t)n * D + j] = v;
        vals[k] = v;
        __nv_bfloat16 h, l; split_bf16(v, h, l);
        cathi[(size_t)n * D2 + j] = h;
        catlo[(size_t)n * D2 + j] = l;
        s += v; sq += v * v;
    }
    __shared__ float rs[256], rq[256];
    rs[tid] = s; rq[tid] = sq; __syncthreads();
    for (int off = 128; off > 0; off >>= 1) {
        if (tid < off) { rs[tid] += rs[tid + off]; rq[tid] += rq[tid + off]; }
        __syncthreads();
    }
    const float mu  = rs[0] * (1.f / D);
    const float var = rq[0] * (1.f / D) - mu * mu;
    const float inv = rsqrtf(var + 1e-6f);
#pragma unroll
    for (int k = 0; k < 4; k++) {
        const int j = tid + k * 256;
        float y = (vals[k] - mu) * inv * g[j] + b[j];
        __nv_bfloat16 h, l; split_bf16(y, h, l);
        lnhi[(size_t)n * D + j] = h;
        lnlo[(size_t)n * D + j] = l;
    }
}

// ---------------- f32 -> hi/lo bf16 split (weights + input) ----------------
__global__ void cvt_split4(const float4* __restrict__ x,
                           __nv_bfloat162* __restrict__ hi, __nv_bfloat162* __restrict__ lo,
                           int n4) {
    int i = blockIdx.x * blockDim.x + threadIdx.x;
    if (i >= n4) return;
    float4 v = x[i];
    __nv_bfloat16 h0, l0, h1, l1, h2, l2, h3, l3;
    split_bf16(v.x, h0, l0); split_bf16(v.y, h1, l1);
    split_bf16(v.z, h2, l2); split_bf16(v.w, h3, l3);
    hi[2*i]   = __halves2bfloat162(h0, h1);
    hi[2*i+1] = __halves2bfloat162(h2, h3);
    lo[2*i]   = __halves2bfloat162(l0, l1);
    lo[2*i+1] = __halves2bfloat162(l2, l3);
}

// ---------------- driver ----------------
extern "C" void kernel_launch(void* const* d_in, const int* in_sizes, int n_in,
                              void* d_out, int out_size) {
    const float* x_in  = (const float*)d_in[0];
    const float* pe    = (const float*)d_in[1];
    const float* in_w  = (const float*)d_in[2];
    const float* in_b  = (const float*)d_in[3];
    const float* qkv_w = (const float*)d_in[4];
    const float* out_w = (const float*)d_in[5];
    const float* out_b = (const float*)d_in[6];
    const float* ln1_g = (const float*)d_in[7];
    const float* ln1_b = (const float*)d_in[8];
    const float* ln2_g = (const float*)d_in[9];
    const float* ln2_b = (const float*)d_in[10];
    const float* ff_w1 = (const float*)d_in[11];
    const float* ff_b1 = (const float*)d_in[12];
    const float* ff_w2 = (const float*)d_in[13];
    const float* ff_b2 = (const float*)d_in[14];
    const float* g1_w  = (const float*)d_in[15];
    const float* g1_bg = (const float*)d_in[16];
    const float* g2_w  = (const float*)d_in[17];
    const float* g2_bg = (const float*)d_in[18];
    const float* on_g  = (const float*)d_in[19];
    const float* on_b  = (const float*)d_in[20];

    float *px, *pqkv, *pgate;
    __nv_bfloat16 *chi, *clo, *lhi, *llo, *phi, *plo, *fhi, *flo, *xhi, *xlo;
    __nv_bfloat16 *w_in_h, *w_in_l, *w_qkv_h, *w_qkv_l, *w_out_h, *w_out_l;
    __nv_bfloat16 *w_f1_h, *w_f1_l, *w_f2_h, *w_f2_l, *w_g1_h, *w_g1_l, *w_g2_h, *w_g2_l;
    cudaGetSymbolAddress((void**)&px,    g_x);
    cudaGetSymbolAddress((void**)&pqkv,  g_qkv);
    cudaGetSymbolAddress((void**)&pgate, g_gate);
    cudaGetSymbolAddress((void**)&chi,   g_chi);  cudaGetSymbolAddress((void**)&clo,   g_clo);
    cudaGetSymbolAddress((void**)&lhi,   g_lhi);  cudaGetSymbolAddress((void**)&llo,   g_llo);
    cudaGetSymbolAddress((void**)&phi,   g_phi);  cudaGetSymbolAddress((void**)&plo,   g_plo);
    cudaGetSymbolAddress((void**)&fhi,   g_fhi);  cudaGetSymbolAddress((void**)&flo,   g_flo);
    cudaGetSymbolAddress((void**)&xhi,   g_xhi);  cudaGetSymbolAddress((void**)&xlo,   g_xlo);
    cudaGetSymbolAddress((void**)&w_in_h,  wb_in_hi);  cudaGetSymbolAddress((void**)&w_in_l,  wb_in_lo);
    cudaGetSymbolAddress((void**)&w_qkv_h, wb_qkv_hi); cudaGetSymbolAddress((void**)&w_qkv_l, wb_qkv_lo);
    cudaGetSymbolAddress((void**)&w_out_h, wb_out_hi); cudaGetSymbolAddress((void**)&w_out_l, wb_out_lo);
    cudaGetSymbolAddress((void**)&w_f1_h,  wb_f1_hi);  cudaGetSymbolAddress((void**)&w_f1_l,  wb_f1_lo);
    cudaGetSymbolAddress((void**)&w_f2_h,  wb_f2_hi);  cudaGetSymbolAddress((void**)&w_f2_l,  wb_f2_lo);
    cudaGetSymbolAddress((void**)&w_g1_h,  wb_g1_hi);  cudaGetSymbolAddress((void**)&w_g1_l,  wb_g1_lo);
    cudaGetSymbolAddress((void**)&w_g2_h,  wb_g2_hi);  cudaGetSymbolAddress((void**)&w_g2_l,  wb_g2_lo);

    cudaFuncSetAttribute(gemm_mma, cudaFuncAttributeMaxDynamicSharedMemorySize, SMEM_BYTES);
    cudaFuncSetAttribute(attn_flash, cudaFuncAttributeMaxDynamicSharedMemorySize, ATTN_SMEM);

    const int EW = 256;
    auto cvtgrid = [](int n) { return (n / 4 + 255) / 256; };

    // ---- weight + input hi/lo splits ----
    cvt_split4<<<cvtgrid(D*D),        EW>>>((const float4*)in_w,  (__nv_bfloat162*)w_in_h,  (__nv_bfloat162*)w_in_l,  D*D/4);
    cvt_split4<<<cvtgrid(LNUM*D3*D),  EW>>>((const float4*)qkv_w, (__nv_bfloat162*)w_qkv_h, (__nv_bfloat162*)w_qkv_l, LNUM*D3*D/4);
    cvt_split4<<<cvtgrid(LNUM*D*D),   EW>>>((const float4*)out_w, (__nv_bfloat162*)w_out_h, (__nv_bfloat162*)w_out_l, LNUM*D*D/4);
    cvt_split4<<<cvtgrid(LNUM*FFD*D), EW>>>((const float4*)ff_w1, (__nv_bfloat162*)w_f1_h,  (__nv_bfloat162*)w_f1_l,  LNUM*FFD*D/4);
    cvt_split4<<<cvtgrid(LNUM*D*FFD), EW>>>((const float4*)ff_w2, (__nv_bfloat162*)w_f2_h,  (__nv_bfloat162*)w_f2_l,  LNUM*D*FFD/4);
    cvt_split4<<<cvtgrid(LNUM*D3*D2), EW>>>((const float4*)g1_w,  (__nv_bfloat162*)w_g1_h,  (__nv_bfloat162*)w_g1_l,  LNUM*D3*D2/4);
    cvt_split4<<<cvtgrid(LNUM*D3*D2), EW>>>((const float4*)g2_w,  (__nv_bfloat162*)w_g2_h,  (__nv_bfloat162*)w_g2_l,  LNUM*D3*D2/4);
    cvt_split4<<<cvtgrid(NTOK*D),     EW>>>((const float4*)x_in,  (__nv_bfloat162*)xhi,     (__nv_bfloat162*)xlo,     NTOK*D/4);

    dim3 gD  (D/128,   NTOK/128);
    dim3 gD3 (D3/128,  NTOK/128);
    dim3 gFF (FFD/128, NTOK/128);

    // ---- input projection, then fused gelu+pe+LN1+splits ----
    gemm_mma<<<gD, 256, SMEM_BYTES>>>(xhi, xlo, D, w_in_h, w_in_l, in_b, px, 0, 0, D, D, 0);
    gelu_pe_ln_split<<<NTOK, 256>>>(px, pe, ln1_g, ln1_b, chi, clo, lhi, llo);

    for (int l = 0; l < LNUM; l++) {
        const __nv_bfloat16* qwh = w_qkv_h + (size_t)l*D3*D;  const __nv_bfloat16* qwl = w_qkv_l + (size_t)l*D3*D;
        const __nv_bfloat16* owh = w_out_h + (size_t)l*D*D;   const __nv_bfloat16* owl = w_out_l + (size_t)l*D*D;
        const __nv_bfloat16* f1h = w_f1_h  + (size_t)l*FFD*D; const __nv_bfloat16* f1l = w_f1_l  + (size_t)l*FFD*D;
        const __nv_bfloat16* f2h = w_f2_h  + (size_t)l*D*FFD; const __nv_bfloat16* f2l = w_f2_l  + (size_t)l*D*FFD;
        const __nv_bfloat16* g1h = w_g1_h  + (size_t)l*D3*D2; const __nv_bfloat16* g1l = w_g1_l  + (size_t)l*D3*D2;
        const __nv_bfloat16* g2h = w_g2_h  + (size_t)l*D3*D2; const __nv_bfloat16* g2l = w_g2_l  + (size_t)l*D3*D2;
        const float* ob  = out_b + (size_t)l*D;
        const float* l2g = ln2_g + (size_t)l*D;  const float* l2b = ln2_b + (size_t)l*D;
        const float* fb1 = ff_b1 + (size_t)l*FFD;
        const float* fb2 = ff_b2 + (size_t)l*D;
        const float* gb1 = g1_bg + (size_t)l*D;
        const float* gb2 = g2_bg + (size_t)l*D;
        // LN after gru2: next layer's ln1, or final output LN
        const float* ng = (l + 1 < LNUM) ? ln1_g + (size_t)(l+1)*D : on_g;
        const float* nb = (l + 1 < LNUM) ? ln1_b + (size_t)(l+1)*D : on_b;
        float* fout = (l + 1 < LNUM) ? nullptr : (float*)d_out;

        // attention block
        gemm_mma<<<gD3, 256, SMEM_BYTES>>>(lhi, llo, D, qwh, qwl, nullptr, pqkv, 0, 0, D3, D, 0);
        attn_flash<<<dim3(TT/QTILE, BATCH*H), 256, ATTN_SMEM>>>(pqkv, phi, plo);
        gemm_mma<<<gD, 256, SMEM_BYTES>>>(phi, plo, D, owh, owl, ob, 0, chi + D, clo + D, D2, D, 2);
        gemm_mma<<<gD3, 256, SMEM_BYTES>>>(chi, clo, D2, g1h, g1l, nullptr, pgate, 0, 0, D3, D2, 0);
        gru_ln_split<<<NTOK, 256>>>(px, pgate, gb1, l2g, l2b, chi, clo, lhi, llo, nullptr);

        // feed-forward block
        gemm_mma<<<gFF, 256, SMEM_BYTES>>>(lhi, llo, D, f1h, f1l, fb1, 0, fhi, flo, FFD, D, 1);
        gemm_mma<<<gD, 256, SMEM_BYTES>>>(fhi, flo, FFD, f2h, f2l, fb2, 0, chi + D, clo + D, D2, FFD, 2);
        gemm_mma<<<gD3, 256, SMEM_BYTES>>>(chi, clo, D2, g2h, g2l, nullptr, pgate, 0, 0, D3, D2, 0);
        gru_ln_split<<<NTOK, 256>>>(px, pgate, gb2, ng, nb, chi, clo, lhi, llo, fout);
    }
}